// round 10
// baseline (speedup 1.0000x reference)
#include <cuda_runtime.h>
#include <cuda_bf16.h>
#include <math.h>
#include <stdint.h>

#define T_TOK 2048
#define H_DIM 1024
#define I_DIM 512
#define N_EXP 16
#define TOPK  4
#define CAP   2048

// ---------------- device scratch ----------------
__device__ int   d_cnt[N_EXP];
__device__ int   d_tok[N_EXP * CAP];
__device__ int   d_slot[N_EXP * CAP];
__device__ float d_wt [N_EXP * CAP];
__device__ __nv_bfloat16 d_xh[T_TOK * H_DIM];
__device__ __nv_bfloat16 d_xl[T_TOK * H_DIM];
__device__ __nv_bfloat16 d_w1h[N_EXP * I_DIM * H_DIM];
__device__ __nv_bfloat16 d_w1l[N_EXP * I_DIM * H_DIM];
__device__ __nv_bfloat16 d_w3h[N_EXP * I_DIM * H_DIM];
__device__ __nv_bfloat16 d_w3l[N_EXP * I_DIM * H_DIM];
__device__ __nv_bfloat16 d_w2h[N_EXP * H_DIM * I_DIM];
__device__ __nv_bfloat16 d_w2l[N_EXP * H_DIM * I_DIM];
__device__ __nv_bfloat16 d_ah[(size_t)N_EXP * CAP * I_DIM];
__device__ __nv_bfloat16 d_al[(size_t)N_EXP * CAP * I_DIM];
__device__ float d_part[(size_t)T_TOK * TOPK * H_DIM];

// ---------------- helpers ----------------
// 64B-row swizzle (Swizzle<2,4,3>): seg bits [5:4] ^= row bits [8:7]
#define SWZ64(o) ((o) ^ (((o) >> 3) & 0x30))

__device__ __forceinline__ uint32_t smem_u32(const void* p) {
    uint32_t a;
    asm("{ .reg .u64 t; cvta.to.shared.u64 t, %1; cvt.u32.u64 %0, t; }" : "=r"(a) : "l"(p));
    return a;
}

#define CP16(sa, ga, sz) \
    asm volatile("cp.async.cg.shared.global [%0], [%1], 16, %2;" \
                 :: "r"(sa), "l"(ga), "r"(sz) : "memory")
#define CP_COMMIT() asm volatile("cp.async.commit_group;" ::: "memory")
#define CP_WAIT(n)  asm volatile("cp.async.wait_group %0;" :: "n"(n) : "memory")

#define LDM4(r0, r1, r2, r3, a) \
    asm volatile("ldmatrix.sync.aligned.m8n8.x4.shared.b16 {%0,%1,%2,%3}, [%4];" \
                 : "=r"(r0), "=r"(r1), "=r"(r2), "=r"(r3) : "r"(a))

#define MMA(d, a, b) \
    asm volatile("mma.sync.aligned.m16n8k16.row.col.f32.bf16.bf16.f32 " \
                 "{%0,%1,%2,%3}, {%4,%5,%6,%7}, {%8,%9}, {%0,%1,%2,%3};" \
                 : "+f"((d)[0]), "+f"((d)[1]), "+f"((d)[2]), "+f"((d)[3]) \
                 : "r"((a)[0]), "r"((a)[1]), "r"((a)[2]), "r"((a)[3]), \
                   "r"((b)[0]), "r"((b)[1]))

// stage layouts (KC=32, 64B rows)
// gemm1: XH 4K | XL 4K | W1H 4K | W1L 4K | W3H 4K | W3L 4K = 24K
#define X1H  0
#define X1L  4096
#define W1H_ 8192
#define W1L_ 12288
#define W3H_ 16384
#define W3L_ 20480
#define S1   24576
#define SMEM1 (4 * S1)
// gemm2: AH 8K | AL 8K | WH 4K | WL 4K = 24K
#define A2H  0
#define A2L  8192
#define W2H_ 16384
#define W2L_ 20480
#define S2   24576
#define SMEM2 (4 * S2)
#define NPAD 68

// ---------------- init ----------------
__global__ void init_k() { if (threadIdx.x < N_EXP) d_cnt[threadIdx.x] = 0; }

// ---------------- fp32 -> bf16 hi/lo split ----------------
__device__ __forceinline__ void split_store(__nv_bfloat16* h, __nv_bfloat16* l, int i, float4 v) {
    __nv_bfloat16 h0 = __float2bfloat16(v.x), h1 = __float2bfloat16(v.y);
    __nv_bfloat16 h2 = __float2bfloat16(v.z), h3 = __float2bfloat16(v.w);
    __nv_bfloat16 l0 = __float2bfloat16(v.x - __bfloat162float(h0));
    __nv_bfloat16 l1 = __float2bfloat16(v.y - __bfloat162float(h1));
    __nv_bfloat16 l2 = __float2bfloat16(v.z - __bfloat162float(h2));
    __nv_bfloat16 l3 = __float2bfloat16(v.w - __bfloat162float(h3));
    ((__nv_bfloat162*)h)[2 * i + 0] = __halves2bfloat162(h0, h1);
    ((__nv_bfloat162*)h)[2 * i + 1] = __halves2bfloat162(h2, h3);
    ((__nv_bfloat162*)l)[2 * i + 0] = __halves2bfloat162(l0, l1);
    ((__nv_bfloat162*)l)[2 * i + 1] = __halves2bfloat162(l2, l3);
}

// ---------------- fused prep: conv w1/w3 + conv x + router ----------------
#define PREP_W_BLOCKS 2048
#define PREP_X_BLOCKS 256
__global__ __launch_bounds__(256) void prep_k(const float* __restrict__ x,
                                              const float* __restrict__ gw,
                                              const float* __restrict__ w1,
                                              const float* __restrict__ w3) {
    const int b = blockIdx.x;
    const int tid = threadIdx.x;

    if (b < PREP_W_BLOCKS) {
        const int n = N_EXP * I_DIM * H_DIM / 4;
        for (int i = b * 256 + tid; i < n; i += PREP_W_BLOCKS * 256) {
            split_store(d_w1h, d_w1l, i, ((const float4*)w1)[i]);
            split_store(d_w3h, d_w3l, i, ((const float4*)w3)[i]);
        }
        return;
    }
    if (b < PREP_W_BLOCKS + PREP_X_BLOCKS) {
        const int b2 = b - PREP_W_BLOCKS;
        const int n = T_TOK * H_DIM / 4;
        for (int i = b2 * 256 + tid; i < n; i += PREP_X_BLOCKS * 256)
            split_store(d_xh, d_xl, i, ((const float4*)x)[i]);
        return;
    }

    // router: one token per block
    __shared__ float xs[H_DIM];
    __shared__ float lg[N_EXP];
    const int t = b - (PREP_W_BLOCKS + PREP_X_BLOCKS);
    const float* xr = x + (size_t)t * H_DIM;
    for (int i = tid; i < H_DIM / 4; i += 256)
        ((float4*)xs)[i] = ((const float4*)xr)[i];
    __syncthreads();

    const int w = tid >> 5, lane = tid & 31;
    #pragma unroll
    for (int j = 0; j < 2; j++) {
        const int e = w * 2 + j;
        const float* g = gw + (size_t)e * H_DIM;
        float s = 0.f;
        for (int h = lane; h < H_DIM; h += 32) s += xs[h] * g[h];
        #pragma unroll
        for (int o = 16; o; o >>= 1) s += __shfl_xor_sync(0xffffffffu, s, o);
        if (lane == 0) lg[e] = s;
    }
    __syncthreads();

    if (tid == 0) {
        int sel[TOPK]; float sl[TOPK];
        unsigned used = 0;
        for (int k = 0; k < TOPK; k++) {
            float best = -1e30f; int bi = 0;
            for (int e = 0; e < N_EXP; e++)
                if (!((used >> e) & 1u) && lg[e] > best) { best = lg[e]; bi = e; }
            used |= 1u << bi; sel[k] = bi; sl[k] = best;
        }
        float m = sl[0], ex[TOPK], sum = 0.f;
        for (int k = 0; k < TOPK; k++) { ex[k] = expf(sl[k] - m); sum += ex[k]; }
        float inv = 1.f / sum;
        for (int k = 0; k < TOPK; k++) {
            int e = sel[k];
            int pos = atomicAdd(&d_cnt[e], 1);
            d_tok [e * CAP + pos] = t;
            d_slot[e * CAP + pos] = k;
            d_wt  [e * CAP + pos] = ex[k] * inv;
        }
    }
}

// ---------------- gemm1: act = silu(X W1^T) * (X W3^T) ----------------
// CTA 64x64, 256 thr; warps 0-3 -> W1, warps 4-7 -> W3 (2x2 each).
// 4-stage cp.async ring, KC=32, one __syncthreads per chunk.
// blockIdx.z == N_EXP: co-scheduled w2 fp32->bf16 split conversion.
__global__ __launch_bounds__(256, 2) void gemm1_t(const float* __restrict__ w2) {
    const int tid = threadIdx.x;
    if (blockIdx.z == N_EXP) {
        const int bid = blockIdx.x * 8 + blockIdx.y;       // 0..255
        const int n = N_EXP * H_DIM * I_DIM / 4;
        for (int i = bid * 256 + tid; i < n; i += 256 * 256)
            split_store(d_w2h, d_w2l, i, ((const float4*)w2)[i]);
        return;
    }

    extern __shared__ char smem[];
    const int e = blockIdx.z, m0 = blockIdx.x * 64, n0 = blockIdx.y * 64;
    const int cnt = d_cnt[e];
    if (m0 >= cnt) return;

    const uint32_t sb = smem_u32(smem);
    const int wid = tid >> 5, lid = tid & 31;
    const int wg = wid >> 2, wl = wid & 3;
    const int wm = wl & 1, wn = wl >> 1;

    __shared__ int toks[64];
    if (tid < 64) toks[tid] = (m0 + tid < cnt) ? d_tok[e * CAP + m0 + tid] : -1;
    __syncthreads();

    const __nv_bfloat16* w1he = d_w1h + ((size_t)e * I_DIM + n0) * H_DIM;
    const __nv_bfloat16* w1le = d_w1l + ((size_t)e * I_DIM + n0) * H_DIM;
    const __nv_bfloat16* w3he = d_w3h + ((size_t)e * I_DIM + n0) * H_DIM;
    const __nv_bfloat16* w3le = d_w3l + ((size_t)e * I_DIM + n0) * H_DIM;

    auto load1 = [&](int c) {
        const uint32_t bo = sb + (c & 3) * S1;
        const int kb = c * 32;
        // 64 rows x 4 segs of 16B; one pass (v = tid < 256)
        {
            const int r = tid >> 2, seg = tid & 3;
            const uint32_t so = SWZ64(r * 64 + seg * 16);
            const int t = toks[r];
            const unsigned p = (t >= 0) ? 16u : 0u;
            const size_t gx = (size_t)(t < 0 ? 0 : t) * H_DIM + kb + seg * 8;
            CP16(bo + X1H + so, d_xh + gx, p);
            CP16(bo + X1L + so, d_xl + gx, p);
            const size_t gwo = (size_t)r * H_DIM + kb + seg * 8;
            CP16(bo + W1H_ + so, w1he + gwo, 16u);
            CP16(bo + W1L_ + so, w1le + gwo, 16u);
            CP16(bo + W3H_ + so, w3he + gwo, 16u);
            CP16(bo + W3L_ + so, w3le + gwo, 16u);
        }
        CP_COMMIT();
    };

    float acc[2][4][4] = {};
    const int ar = lid & 15, ac = (lid >> 4) * 8;
    const int bq = lid >> 3, brr = lid & 7;
    const int bn = (bq >> 1) * 8 + brr, bk = (bq & 1) * 8;
    const uint32_t wBh = wg ? W3H_ : W1H_;
    const uint32_t wBl = wg ? W3L_ : W1L_;

    const int NCH = H_DIM / 32;   // 32
    load1(0); load1(1);
    for (int c = 0; c < NCH; c++) {
        if (c + 2 < NCH) { load1(c + 2); CP_WAIT(2); }
        else if (c + 1 < NCH) { CP_WAIT(1); }
        else { CP_WAIT(0); }
        __syncthreads();
        const uint32_t bo = sb + (c & 3) * S1;

        #pragma unroll
        for (int ks = 0; ks < 2; ks++) {
            const int k = ks * 16;
            uint32_t ah[2][4], al[2][4];
            #pragma unroll
            for (int mi = 0; mi < 2; mi++) {
                const uint32_t off = SWZ64((wm * 32 + mi * 16 + ar) * 64 + (k + ac) * 2);
                LDM4(ah[mi][0], ah[mi][1], ah[mi][2], ah[mi][3], bo + X1H + off);
                LDM4(al[mi][0], al[mi][1], al[mi][2], al[mi][3], bo + X1L + off);
            }
            #pragma unroll
            for (int nh = 0; nh < 2; nh++) {
                const uint32_t off = SWZ64((wn * 32 + nh * 16 + bn) * 64 + (k + bk) * 2);
                uint32_t bh[4], bl[4];
                LDM4(bh[0], bh[1], bh[2], bh[3], bo + wBh + off);
                LDM4(bl[0], bl[1], bl[2], bl[3], bo + wBl + off);
                #pragma unroll
                for (int mi = 0; mi < 2; mi++)
                    #pragma unroll
                    for (int j = 0; j < 2; j++) {
                        const int nj = 2 * nh + j;
                        MMA(acc[mi][nj], ah[mi], bh + 2 * j);
                        MMA(acc[mi][nj], ah[mi], bl + 2 * j);
                        MMA(acc[mi][nj], al[mi], bh + 2 * j);
                    }
            }
        }
    }
    __syncthreads();

    // exchange: w3-group stores acc to smem; w1-group fuses silu*mul and writes act
    float* xch = (float*)smem;   // 64 x NPAD floats, reuses stage smem
    const int g = lid >> 2, tg = lid & 3;
    if (wg == 1) {
        #pragma unroll
        for (int mi = 0; mi < 2; mi++)
            #pragma unroll
            for (int sub = 0; sub < 2; sub++) {
                const int r = wm * 32 + mi * 16 + sub * 8 + g;
                #pragma unroll
                for (int nj = 0; nj < 4; nj++) {
                    const int cc = wn * 32 + nj * 8 + 2 * tg;
                    *(float2*)&xch[r * NPAD + cc] =
                        make_float2(acc[mi][nj][2 * sub], acc[mi][nj][2 * sub + 1]);
                }
            }
    }
    __syncthreads();
    if (wg == 0) {
        #pragma unroll
        for (int mi = 0; mi < 2; mi++)
            #pragma unroll
            for (int sub = 0; sub < 2; sub++) {
                const int mr = wm * 32 + mi * 16 + sub * 8 + g;
                const int m = m0 + mr;
                if (m >= cnt) continue;
                const size_t arow = ((size_t)e * CAP + m) * I_DIM + n0;
                #pragma unroll
                for (int nj = 0; nj < 4; nj++) {
                    const int cc = wn * 32 + nj * 8 + 2 * tg;
                    float2 g3 = *(float2*)&xch[mr * NPAD + cc];
                    float h0 = acc[mi][nj][2 * sub], h1 = acc[mi][nj][2 * sub + 1];
                    float v0 = (h0 / (1.f + expf(-h0))) * g3.x;
                    float v1 = (h1 / (1.f + expf(-h1))) * g3.y;
                    __nv_bfloat16 a0 = __float2bfloat16(v0), a1 = __float2bfloat16(v1);
                    __nv_bfloat16 b0 = __float2bfloat16(v0 - __bfloat162float(a0));
                    __nv_bfloat16 b1 = __float2bfloat16(v1 - __bfloat162float(a1));
                    *(__nv_bfloat162*)(d_ah + arow + cc) = __halves2bfloat162(a0, a1);
                    *(__nv_bfloat162*)(d_al + arow + cc) = __halves2bfloat162(b0, b1);
                }
            }
    }
}

// ---------------- gemm2: part[t][slot] = w * (act W2^T), CTA 128x64 ----------------
__global__ __launch_bounds__(256, 2) void gemm2_t() {
    extern __shared__ char smem[];
    const int e = blockIdx.z, m0 = blockIdx.x * 128, n0 = blockIdx.y * 64;  // n over H
    const int cnt = d_cnt[e];
    if (m0 >= cnt) return;

    const uint32_t sb = smem_u32(smem);
    const int tid = threadIdx.x, wid = tid >> 5, lid = tid & 31;
    const int wm = wid & 3, wn = wid >> 2;   // 4x2 warp grid

    __shared__ int   toks[128];
    __shared__ int   slots[128];
    __shared__ float wts[128];
    if (tid < 128) {
        const int m = m0 + tid;
        const bool v = (m < cnt);
        toks [tid] = v ? d_tok [e * CAP + m] : 0;
        slots[tid] = v ? d_slot[e * CAP + m] : 0;
        wts  [tid] = v ? d_wt  [e * CAP + m] : 0.f;
    }
    __syncthreads();

    const __nv_bfloat16* whe = d_w2h + ((size_t)e * H_DIM + n0) * I_DIM;
    const __nv_bfloat16* wle = d_w2l + ((size_t)e * H_DIM + n0) * I_DIM;
    const size_t abase = ((size_t)e * CAP + m0) * I_DIM;

    auto load2 = [&](int c) {
        const uint32_t bo = sb + (c & 3) * S2;
        const int kb = c * 32;
        #pragma unroll
        for (int v = tid; v < 128 * 4; v += 256) {
            const int r = v >> 2, seg = v & 3;
            const uint32_t so = SWZ64(r * 64 + seg * 16);
            const unsigned p = (m0 + r < cnt) ? 16u : 0u;
            const size_t ga = abase + (size_t)r * I_DIM + kb + seg * 8;
            CP16(bo + A2H + so, d_ah + ga, p);
            CP16(bo + A2L + so, d_al + ga, p);
            if (v < 256) {
                const size_t gwo = (size_t)r * I_DIM + kb + seg * 8;
                CP16(bo + W2H_ + so, whe + gwo, 16u);
                CP16(bo + W2L_ + so, wle + gwo, 16u);
            }
        }
        CP_COMMIT();
    };

    float acc[2][4][4] = {};
    const int ar = lid & 15, ac = (lid >> 4) * 8;
    const int bq = lid >> 3, brr = lid & 7;
    const int bn = (bq >> 1) * 8 + brr, bk = (bq & 1) * 8;

    const int NCH = I_DIM / 32;   // 16
    load2(0); load2(1);
    for (int c = 0; c < NCH; c++) {
        if (c + 2 < NCH) { load2(c + 2); CP_WAIT(2); }
        else if (c + 1 < NCH) { CP_WAIT(1); }
        else { CP_WAIT(0); }
        __syncthreads();
        const uint32_t bo = sb + (c & 3) * S2;

        #pragma unroll
        for (int ks = 0; ks < 2; ks++) {
            const int k = ks * 16;
            uint32_t ah[2][4], al[2][4];
            #pragma unroll
            for (int mi = 0; mi < 2; mi++) {
                const uint32_t off = SWZ64((wm * 32 + mi * 16 + ar) * 64 + (k + ac) * 2);
                LDM4(ah[mi][0], ah[mi][1], ah[mi][2], ah[mi][3], bo + A2H + off);
                LDM4(al[mi][0], al[mi][1], al[mi][2], al[mi][3], bo + A2L + off);
            }
            #pragma unroll
            for (int nh = 0; nh < 2; nh++) {
                const uint32_t off = SWZ64((wn * 32 + nh * 16 + bn) * 64 + (k + bk) * 2);
                uint32_t bh[4], bl[4];
                LDM4(bh[0], bh[1], bh[2], bh[3], bo + W2H_ + off);
                LDM4(bl[0], bl[1], bl[2], bl[3], bo + W2L_ + off);
                #pragma unroll
                for (int mi = 0; mi < 2; mi++)
                    #pragma unroll
                    for (int j = 0; j < 2; j++) {
                        const int nj = 2 * nh + j;
                        MMA(acc[mi][nj], ah[mi], bh + 2 * j);
                        MMA(acc[mi][nj], ah[mi], bl + 2 * j);
                        MMA(acc[mi][nj], al[mi], bh + 2 * j);
                    }
            }
        }
    }

    const int g = lid >> 2, tg = lid & 3;
    #pragma unroll
    for (int mi = 0; mi < 2; mi++)
        #pragma unroll
        for (int sub = 0; sub < 2; sub++) {
            const int mrow = wm * 32 + mi * 16 + sub * 8 + g;
            if (m0 + mrow >= cnt) continue;
            const int t = toks[mrow], sk = slots[mrow];
            const float wv = wts[mrow];
            const size_t pbase = ((size_t)t * TOPK + sk) * H_DIM + n0 + wn * 32;
            #pragma unroll
            for (int nj = 0; nj < 4; nj++) {
                float2 o;
                o.x = wv * acc[mi][nj][2 * sub];
                o.y = wv * acc[mi][nj][2 * sub + 1];
                *(float2*)(d_part + pbase + nj * 8 + 2 * tg) = o;
            }
        }
}

// ---------------- combine ----------------
__global__ __launch_bounds__(256) void combine_k(float* __restrict__ out) {
    const int idx = blockIdx.x * blockDim.x + threadIdx.x;
    const int t = idx >> 8, c4 = idx & 255;
    const float4* p = (const float4*)d_part + (size_t)t * TOPK * 256 + c4;
    float4 a = p[0], b = p[256], c = p[512], d = p[768];
    float4 o;
    o.x = a.x + b.x + c.x + d.x;
    o.y = a.y + b.y + c.y + d.y;
    o.z = a.z + b.z + c.z + d.z;
    o.w = a.w + b.w + c.w + d.w;
    ((float4*)out)[idx] = o;
}

// ---------------- launch ----------------
extern "C" void kernel_launch(void* const* d_in, const int* in_sizes, int n_in,
                              void* d_out, int out_size) {
    const float* x  = (const float*)d_in[0];
    const float* gw = (const float*)d_in[1];
    const float* w1 = (const float*)d_in[2];
    const float* w3 = (const float*)d_in[3];
    const float* w2 = (const float*)d_in[4];
    float* out = (float*)d_out;

    cudaFuncSetAttribute(gemm1_t, cudaFuncAttributeMaxDynamicSharedMemorySize, SMEM1);
    cudaFuncSetAttribute(gemm2_t, cudaFuncAttributeMaxDynamicSharedMemorySize, SMEM2);

    init_k<<<1, 32>>>();
    prep_k<<<PREP_W_BLOCKS + PREP_X_BLOCKS + T_TOK, 256>>>(x, gw, w1, w3);
    gemm1_t<<<dim3(CAP / 64, I_DIM / 64, N_EXP + 1), 256, SMEM1>>>(w2);
    gemm2_t<<<dim3(CAP / 128, H_DIM / 64, N_EXP), 256, SMEM2>>>();
    combine_k<<<T_TOK, 256>>>(out);
}

// round 11
// speedup vs baseline: 1.5362x; 1.5362x over previous
#include <cuda_runtime.h>
#include <cuda_bf16.h>
#include <math.h>
#include <stdint.h>

#define T_TOK 2048
#define H_DIM 1024
#define I_DIM 512
#define N_EXP 16
#define TOPK  4
#define CAP   2048
#define KC 64

// ---------------- device scratch ----------------
__device__ int   d_cnt[N_EXP];
__device__ int   d_tok[N_EXP * CAP];
__device__ int   d_slot[N_EXP * CAP];
__device__ float d_wt [N_EXP * CAP];
__device__ __nv_bfloat16 d_xh[T_TOK * H_DIM];
__device__ __nv_bfloat16 d_xl[T_TOK * H_DIM];
__device__ __nv_bfloat16 d_w1h[N_EXP * I_DIM * H_DIM];
__device__ __nv_bfloat16 d_w1l[N_EXP * I_DIM * H_DIM];
__device__ __nv_bfloat16 d_w3h[N_EXP * I_DIM * H_DIM];
__device__ __nv_bfloat16 d_w3l[N_EXP * I_DIM * H_DIM];
__device__ __nv_bfloat16 d_w2h[N_EXP * H_DIM * I_DIM];
__device__ __nv_bfloat16 d_w2l[N_EXP * H_DIM * I_DIM];
__device__ __nv_bfloat16 d_ah[(size_t)N_EXP * CAP * I_DIM];
__device__ __nv_bfloat16 d_al[(size_t)N_EXP * CAP * I_DIM];
__device__ float d_part[(size_t)T_TOK * TOPK * H_DIM];

// ---------------- helpers ----------------
#define SWZ(o) ((o) ^ (((o) >> 3) & 0x70))

__device__ __forceinline__ uint32_t smem_u32(const void* p) {
    uint32_t a;
    asm("{ .reg .u64 t; cvta.to.shared.u64 t, %1; cvt.u32.u64 %0, t; }" : "=r"(a) : "l"(p));
    return a;
}

#define CP16(sa, ga, sz) \
    asm volatile("cp.async.cg.shared.global [%0], [%1], 16, %2;" \
                 :: "r"(sa), "l"(ga), "r"(sz) : "memory")
#define CP_COMMIT() asm volatile("cp.async.commit_group;" ::: "memory")
#define CP_WAIT(n)  asm volatile("cp.async.wait_group %0;" :: "n"(n) : "memory")

#define LDM4(r0, r1, r2, r3, a) \
    asm volatile("ldmatrix.sync.aligned.m8n8.x4.shared.b16 {%0,%1,%2,%3}, [%4];" \
                 : "=r"(r0), "=r"(r1), "=r"(r2), "=r"(r3) : "r"(a))

#define MMA(d, a, b) \
    asm volatile("mma.sync.aligned.m16n8k16.row.col.f32.bf16.bf16.f32 " \
                 "{%0,%1,%2,%3}, {%4,%5,%6,%7}, {%8,%9}, {%0,%1,%2,%3};" \
                 : "+f"((d)[0]), "+f"((d)[1]), "+f"((d)[2]), "+f"((d)[3]) \
                 : "r"((a)[0]), "r"((a)[1]), "r"((a)[2]), "r"((a)[3]), \
                   "r"((b)[0]), "r"((b)[1]))

// smem layouts (per stage buffer)
// gemm1 (CTA 64x64): XH 8K | XL 8K | W1H 8K | W1L 8K | W3H 8K | W3L 8K = 48K
#define G1_XH  0
#define G1_XL  8192
#define G1_W1H 16384
#define G1_W1L 24576
#define G1_W3H 32768
#define G1_W3L 40960
#define G1_BUF 49152
#define SMEM1 (2 * G1_BUF)
// gemm2 (CTA 128x64): AH 16K | AL 16K | WH 8K | WL 8K = 48K
#define G2_AH  0
#define G2_AL  16384
#define G2_WH  32768
#define G2_WL  40960
#define G2_BUF 49152
#define SMEM2 (2 * G2_BUF)
#define NPAD 68

// ---------------- init ----------------
__global__ void init_k() { if (threadIdx.x < N_EXP) d_cnt[threadIdx.x] = 0; }

// ---------------- fp32 -> bf16 hi/lo split ----------------
__device__ __forceinline__ void split_store(__nv_bfloat16* h, __nv_bfloat16* l, int i, float4 v) {
    __nv_bfloat16 h0 = __float2bfloat16(v.x), h1 = __float2bfloat16(v.y);
    __nv_bfloat16 h2 = __float2bfloat16(v.z), h3 = __float2bfloat16(v.w);
    __nv_bfloat16 l0 = __float2bfloat16(v.x - __bfloat162float(h0));
    __nv_bfloat16 l1 = __float2bfloat16(v.y - __bfloat162float(h1));
    __nv_bfloat16 l2 = __float2bfloat16(v.z - __bfloat162float(h2));
    __nv_bfloat16 l3 = __float2bfloat16(v.w - __bfloat162float(h3));
    ((__nv_bfloat162*)h)[2 * i + 0] = __halves2bfloat162(h0, h1);
    ((__nv_bfloat162*)h)[2 * i + 1] = __halves2bfloat162(h2, h3);
    ((__nv_bfloat162*)l)[2 * i + 0] = __halves2bfloat162(l0, l1);
    ((__nv_bfloat162*)l)[2 * i + 1] = __halves2bfloat162(l2, l3);
}

// ---------------- fused prep: conv w1/w3 + conv x + router (no w2) ----------------
#define PREP_W_BLOCKS 2048
#define PREP_X_BLOCKS 256
__global__ __launch_bounds__(256) void prep_k(const float* __restrict__ x,
                                              const float* __restrict__ gw,
                                              const float* __restrict__ w1,
                                              const float* __restrict__ w3) {
    const int b = blockIdx.x;
    const int tid = threadIdx.x;

    if (b < PREP_W_BLOCKS) {
        const int n = N_EXP * I_DIM * H_DIM / 4;
        for (int i = b * 256 + tid; i < n; i += PREP_W_BLOCKS * 256) {
            split_store(d_w1h, d_w1l, i, ((const float4*)w1)[i]);
            split_store(d_w3h, d_w3l, i, ((const float4*)w3)[i]);
        }
        return;
    }
    if (b < PREP_W_BLOCKS + PREP_X_BLOCKS) {
        const int b2 = b - PREP_W_BLOCKS;
        const int n = T_TOK * H_DIM / 4;
        for (int i = b2 * 256 + tid; i < n; i += PREP_X_BLOCKS * 256)
            split_store(d_xh, d_xl, i, ((const float4*)x)[i]);
        return;
    }

    // router: one token per block
    __shared__ float xs[H_DIM];
    __shared__ float lg[N_EXP];
    const int t = b - (PREP_W_BLOCKS + PREP_X_BLOCKS);
    const float* xr = x + (size_t)t * H_DIM;
    for (int i = tid; i < H_DIM / 4; i += 256)
        ((float4*)xs)[i] = ((const float4*)xr)[i];
    __syncthreads();

    const int w = tid >> 5, lane = tid & 31;
    #pragma unroll
    for (int j = 0; j < 2; j++) {
        const int e = w * 2 + j;
        const float* g = gw + (size_t)e * H_DIM;
        float s = 0.f;
        for (int h = lane; h < H_DIM; h += 32) s += xs[h] * g[h];
        #pragma unroll
        for (int o = 16; o; o >>= 1) s += __shfl_xor_sync(0xffffffffu, s, o);
        if (lane == 0) lg[e] = s;
    }
    __syncthreads();

    if (tid == 0) {
        int sel[TOPK]; float sl[TOPK];
        unsigned used = 0;
        for (int k = 0; k < TOPK; k++) {
            float best = -1e30f; int bi = 0;
            for (int e = 0; e < N_EXP; e++)
                if (!((used >> e) & 1u) && lg[e] > best) { best = lg[e]; bi = e; }
            used |= 1u << bi; sel[k] = bi; sl[k] = best;
        }
        float m = sl[0], ex[TOPK], sum = 0.f;
        for (int k = 0; k < TOPK; k++) { ex[k] = expf(sl[k] - m); sum += ex[k]; }
        float inv = 1.f / sum;
        for (int k = 0; k < TOPK; k++) {
            int e = sel[k];
            int pos = atomicAdd(&d_cnt[e], 1);
            d_tok [e * CAP + pos] = t;
            d_slot[e * CAP + pos] = k;
            d_wt  [e * CAP + pos] = ex[k] * inv;
        }
    }
}

// ---------------- gemm1: act = silu(X W1^T) * (X W3^T) ----------------
// 256 threads, CTA tile 64x64. Warps 0-3 -> X*W1, warps 4-7 -> X*W3 (2x2 each).
// blockIdx.z == N_EXP: co-scheduled w2 fp32->bf16 split conversion (pure memory).
__global__ __launch_bounds__(256, 2) void gemm1_t(const float* __restrict__ w2) {
    const int tid = threadIdx.x;
    if (blockIdx.z == N_EXP) {
        const int bid = blockIdx.x * 8 + blockIdx.y;       // 0..255
        const int n = N_EXP * H_DIM * I_DIM / 4;
        for (int i = bid * 256 + tid; i < n; i += 256 * 256)
            split_store(d_w2h, d_w2l, i, ((const float4*)w2)[i]);
        return;
    }

    extern __shared__ char smem[];
    const int e = blockIdx.z, m0 = blockIdx.x * 64, n0 = blockIdx.y * 64;
    const int cnt = d_cnt[e];
    if (m0 >= cnt) return;

    const uint32_t sb = smem_u32(smem);
    const int wid = tid >> 5, lid = tid & 31;
    const int wg = wid >> 2, wl = wid & 3;
    const int wm = wl & 1, wn = wl >> 1;   // 2x2 warp grid per group

    __shared__ int toks[64];
    if (tid < 64) toks[tid] = (m0 + tid < cnt) ? d_tok[e * CAP + m0 + tid] : -1;
    __syncthreads();

    const __nv_bfloat16* w1he = d_w1h + ((size_t)e * I_DIM + n0) * H_DIM;
    const __nv_bfloat16* w1le = d_w1l + ((size_t)e * I_DIM + n0) * H_DIM;
    const __nv_bfloat16* w3he = d_w3h + ((size_t)e * I_DIM + n0) * H_DIM;
    const __nv_bfloat16* w3le = d_w3l + ((size_t)e * I_DIM + n0) * H_DIM;

    auto load1 = [&](int c, int b) {
        const uint32_t bo = sb + b * G1_BUF;
        const int kb = c * KC;
        #pragma unroll
        for (int v = tid; v < 64 * 8; v += 256) {
            const int r = v >> 3, seg = v & 7;
            const uint32_t so = SWZ(r * 128 + seg * 16);
            const int t = toks[r];
            const unsigned p = (t >= 0) ? 16u : 0u;
            const size_t go = (size_t)(t < 0 ? 0 : t) * H_DIM + kb + seg * 8;
            CP16(bo + G1_XH + so, d_xh + go, p);
            CP16(bo + G1_XL + so, d_xl + go, p);
        }
        #pragma unroll
        for (int v = tid; v < 64 * 8; v += 256) {
            const int r = v >> 3, seg = v & 7;
            const uint32_t so = SWZ(r * 128 + seg * 16);
            const size_t go = (size_t)r * H_DIM + kb + seg * 8;
            CP16(bo + G1_W1H + so, w1he + go, 16u);
            CP16(bo + G1_W1L + so, w1le + go, 16u);
            CP16(bo + G1_W3H + so, w3he + go, 16u);
            CP16(bo + G1_W3L + so, w3le + go, 16u);
        }
        CP_COMMIT();
    };

    float acc[2][4][4] = {};
    const int ar = lid & 15, ac = (lid >> 4) * 8;
    const int bq = lid >> 3, brr = lid & 7;
    const int bn = (bq >> 1) * 8 + brr, bk = (bq & 1) * 8;
    const uint32_t wBh = wg ? G1_W3H : G1_W1H;
    const uint32_t wBl = wg ? G1_W3L : G1_W1L;

    load1(0, 0);
    const int NCH = H_DIM / KC;   // 16
    for (int c = 0; c < NCH; c++) {
        const int b = c & 1;
        if (c + 1 < NCH) { load1(c + 1, (c + 1) & 1); CP_WAIT(1); }
        else CP_WAIT(0);
        __syncthreads();
        const uint32_t bo = sb + b * G1_BUF;

        #pragma unroll
        for (int ks = 0; ks < 4; ks++) {
            const int k = ks * 16;
            uint32_t ah[2][4], al[2][4];
            #pragma unroll
            for (int mi = 0; mi < 2; mi++) {
                const uint32_t off = SWZ((wm * 32 + mi * 16 + ar) * 128 + (k + ac) * 2);
                LDM4(ah[mi][0], ah[mi][1], ah[mi][2], ah[mi][3], bo + G1_XH + off);
                LDM4(al[mi][0], al[mi][1], al[mi][2], al[mi][3], bo + G1_XL + off);
            }
            #pragma unroll
            for (int nh = 0; nh < 2; nh++) {
                const uint32_t off = SWZ((wn * 32 + nh * 16 + bn) * 128 + (k + bk) * 2);
                uint32_t bh[4], bl[4];
                LDM4(bh[0], bh[1], bh[2], bh[3], bo + wBh + off);
                LDM4(bl[0], bl[1], bl[2], bl[3], bo + wBl + off);
                #pragma unroll
                for (int mi = 0; mi < 2; mi++)
                    #pragma unroll
                    for (int j = 0; j < 2; j++) {
                        const int nj = 2 * nh + j;
                        MMA(acc[mi][nj], ah[mi], bh + 2 * j);
                        MMA(acc[mi][nj], ah[mi], bl + 2 * j);
                        MMA(acc[mi][nj], al[mi], bh + 2 * j);
                    }
            }
        }
        __syncthreads();
    }

    // exchange: w3-group stores acc to smem; w1-group fuses silu*mul and writes act
    float* xch = (float*)smem;   // 64 x NPAD floats, reuses stage smem
    const int g = lid >> 2, tg = lid & 3;
    if (wg == 1) {
        #pragma unroll
        for (int mi = 0; mi < 2; mi++)
            #pragma unroll
            for (int sub = 0; sub < 2; sub++) {
                const int r = wm * 32 + mi * 16 + sub * 8 + g;
                #pragma unroll
                for (int nj = 0; nj < 4; nj++) {
                    const int cc = wn * 32 + nj * 8 + 2 * tg;
                    *(float2*)&xch[r * NPAD + cc] =
                        make_float2(acc[mi][nj][2 * sub], acc[mi][nj][2 * sub + 1]);
                }
            }
    }
    __syncthreads();
    if (wg == 0) {
        #pragma unroll
        for (int mi = 0; mi < 2; mi++)
            #pragma unroll
            for (int sub = 0; sub < 2; sub++) {
                const int mr = wm * 32 + mi * 16 + sub * 8 + g;
                const int m = m0 + mr;
                if (m >= cnt) continue;
                const size_t arow = ((size_t)e * CAP + m) * I_DIM + n0;
                #pragma unroll
                for (int nj = 0; nj < 4; nj++) {
                    const int cc = wn * 32 + nj * 8 + 2 * tg;
                    float2 g3 = *(float2*)&xch[mr * NPAD + cc];
                    float h0 = acc[mi][nj][2 * sub], h1 = acc[mi][nj][2 * sub + 1];
                    float v0 = (h0 / (1.f + expf(-h0))) * g3.x;
                    float v1 = (h1 / (1.f + expf(-h1))) * g3.y;
                    __nv_bfloat16 a0 = __float2bfloat16(v0), a1 = __float2bfloat16(v1);
                    __nv_bfloat16 b0 = __float2bfloat16(v0 - __bfloat162float(a0));
                    __nv_bfloat16 b1 = __float2bfloat16(v1 - __bfloat162float(a1));
                    *(__nv_bfloat162*)(d_ah + arow + cc) = __halves2bfloat162(a0, a1);
                    *(__nv_bfloat162*)(d_al + arow + cc) = __halves2bfloat162(b0, b1);
                }
            }
    }
}

// ---------------- gemm2: part[t][slot] = w * (act W2^T), CTA 128x64, 256 thr ----------------
__global__ __launch_bounds__(256, 2) void gemm2_t() {
    extern __shared__ char smem[];
    const int e = blockIdx.z, m0 = blockIdx.x * 128, n0 = blockIdx.y * 64;  // n over H
    const int cnt = d_cnt[e];
    if (m0 >= cnt) return;

    const uint32_t sb = smem_u32(smem);
    const int tid = threadIdx.x, wid = tid >> 5, lid = tid & 31;
    const int wm = wid & 3, wn = wid >> 2;   // 4x2 warp grid

    __shared__ int   toks[128];
    __shared__ int   slots[128];
    __shared__ float wts[128];
    if (tid < 128) {
        const int m = m0 + tid;
        const bool v = (m < cnt);
        toks [tid] = v ? d_tok [e * CAP + m] : 0;
        slots[tid] = v ? d_slot[e * CAP + m] : 0;
        wts  [tid] = v ? d_wt  [e * CAP + m] : 0.f;
    }
    __syncthreads();

    const __nv_bfloat16* whe = d_w2h + ((size_t)e * H_DIM + n0) * I_DIM;
    const __nv_bfloat16* wle = d_w2l + ((size_t)e * H_DIM + n0) * I_DIM;
    const size_t abase = ((size_t)e * CAP + m0) * I_DIM;

    auto load2 = [&](int c, int b) {
        const uint32_t bo = sb + b * G2_BUF;
        const int kb = c * KC;
        #pragma unroll
        for (int v = tid; v < 128 * 8; v += 256) {
            const int r = v >> 3, seg = v & 7;
            const uint32_t so = SWZ(r * 128 + seg * 16);
            const unsigned p = (m0 + r < cnt) ? 16u : 0u;
            const size_t go = abase + (size_t)r * I_DIM + kb + seg * 8;
            CP16(bo + G2_AH + so, d_ah + go, p);
            CP16(bo + G2_AL + so, d_al + go, p);
        }
        #pragma unroll
        for (int v = tid; v < 64 * 8; v += 256) {
            const int r = v >> 3, seg = v & 7;
            const uint32_t so = SWZ(r * 128 + seg * 16);
            const size_t go = (size_t)r * I_DIM + kb + seg * 8;
            CP16(bo + G2_WH + so, whe + go, 16u);
            CP16(bo + G2_WL + so, wle + go, 16u);
        }
        CP_COMMIT();
    };

    float acc[2][4][4] = {};
    const int ar = lid & 15, ac = (lid >> 4) * 8;
    const int bq = lid >> 3, brr = lid & 7;
    const int bn = (bq >> 1) * 8 + brr, bk = (bq & 1) * 8;

    load2(0, 0);
    const int NCH = I_DIM / KC;   // 8
    for (int c = 0; c < NCH; c++) {
        const int b = c & 1;
        if (c + 1 < NCH) { load2(c + 1, (c + 1) & 1); CP_WAIT(1); }
        else CP_WAIT(0);
        __syncthreads();
        const uint32_t bo = sb + b * G2_BUF;

        #pragma unroll
        for (int ks = 0; ks < 4; ks++) {
            const int k = ks * 16;
            uint32_t ah[2][4], al[2][4];
            #pragma unroll
            for (int mi = 0; mi < 2; mi++) {
                const uint32_t off = SWZ((wm * 32 + mi * 16 + ar) * 128 + (k + ac) * 2);
                LDM4(ah[mi][0], ah[mi][1], ah[mi][2], ah[mi][3], bo + G2_AH + off);
                LDM4(al[mi][0], al[mi][1], al[mi][2], al[mi][3], bo + G2_AL + off);
            }
            #pragma unroll
            for (int nh = 0; nh < 2; nh++) {
                const uint32_t off = SWZ((wn * 32 + nh * 16 + bn) * 128 + (k + bk) * 2);
                uint32_t bh[4], bl[4];
                LDM4(bh[0], bh[1], bh[2], bh[3], bo + G2_WH + off);
                LDM4(bl[0], bl[1], bl[2], bl[3], bo + G2_WL + off);
                #pragma unroll
                for (int mi = 0; mi < 2; mi++)
                    #pragma unroll
                    for (int j = 0; j < 2; j++) {
                        const int nj = 2 * nh + j;
                        MMA(acc[mi][nj], ah[mi], bh + 2 * j);
                        MMA(acc[mi][nj], ah[mi], bl + 2 * j);
                        MMA(acc[mi][nj], al[mi], bh + 2 * j);
                    }
            }
        }
        __syncthreads();
    }

    const int g = lid >> 2, tg = lid & 3;
    #pragma unroll
    for (int mi = 0; mi < 2; mi++)
        #pragma unroll
        for (int sub = 0; sub < 2; sub++) {
            const int mrow = wm * 32 + mi * 16 + sub * 8 + g;
            if (m0 + mrow >= cnt) continue;
            const int t = toks[mrow], sk = slots[mrow];
            const float wv = wts[mrow];
            const size_t pbase = ((size_t)t * TOPK + sk) * H_DIM + n0 + wn * 32;
            #pragma unroll
            for (int nj = 0; nj < 4; nj++) {
                float2 o;
                o.x = wv * acc[mi][nj][2 * sub];
                o.y = wv * acc[mi][nj][2 * sub + 1];
                *(float2*)(d_part + pbase + nj * 8 + 2 * tg) = o;
            }
        }
}

// ---------------- combine ----------------
__global__ __launch_bounds__(256) void combine_k(float* __restrict__ out) {
    const int idx = blockIdx.x * blockDim.x + threadIdx.x;
    const int t = idx >> 8, c4 = idx & 255;
    const float4* p = (const float4*)d_part + (size_t)t * TOPK * 256 + c4;
    float4 a = p[0], b = p[256], c = p[512], d = p[768];
    float4 o;
    o.x = a.x + b.x + c.x + d.x;
    o.y = a.y + b.y + c.y + d.y;
    o.z = a.z + b.z + c.z + d.z;
    o.w = a.w + b.w + c.w + d.w;
    ((float4*)out)[idx] = o;
}

// ---------------- launch ----------------
extern "C" void kernel_launch(void* const* d_in, const int* in_sizes, int n_in,
                              void* d_out, int out_size) {
    const float* x  = (const float*)d_in[0];
    const float* gw = (const float*)d_in[1];
    const float* w1 = (const float*)d_in[2];
    const float* w3 = (const float*)d_in[3];
    const float* w2 = (const float*)d_in[4];
    float* out = (float*)d_out;

    cudaFuncSetAttribute(gemm1_t, cudaFuncAttributeMaxDynamicSharedMemorySize, SMEM1);
    cudaFuncSetAttribute(gemm2_t, cudaFuncAttributeMaxDynamicSharedMemorySize, SMEM2);

    init_k<<<1, 32>>>();
    prep_k<<<PREP_W_BLOCKS + PREP_X_BLOCKS + T_TOK, 256>>>(x, gw, w1, w3);
    gemm1_t<<<dim3(CAP / 64, I_DIM / 64, N_EXP + 1), 256, SMEM1>>>(w2);
    gemm2_t<<<dim3(CAP / 128, H_DIM / 64, N_EXP), 256, SMEM2>>>();
    combine_k<<<T_TOK, 256>>>(out);
}

// round 13
// speedup vs baseline: 1.5518x; 1.0102x over previous
#include <cuda_runtime.h>
#include <cuda_bf16.h>
#include <math.h>
#include <stdint.h>

#define T_TOK 2048
#define H_DIM 1024
#define I_DIM 512
#define N_EXP 16
#define TOPK  4
#define CAP   2048

// interleaved hi/lo layout: logical row of R elements -> 2R bf16,
// element g: hi at row*2R + (g>>5)*64 + (g&31), lo at +32.
__device__ int   d_cnt[N_EXP];
__device__ int   d_tok[N_EXP * CAP];
__device__ int   d_slot[N_EXP * CAP];
__device__ float d_wt [N_EXP * CAP];
__device__ __nv_bfloat16 d_xi [(size_t)T_TOK * 2 * H_DIM];
__device__ __nv_bfloat16 d_w1i[(size_t)N_EXP * I_DIM * 2 * H_DIM];
__device__ __nv_bfloat16 d_w3i[(size_t)N_EXP * I_DIM * 2 * H_DIM];
__device__ __nv_bfloat16 d_w2i[(size_t)N_EXP * H_DIM * 2 * I_DIM];
__device__ __nv_bfloat16 d_ai [(size_t)N_EXP * CAP * 2 * I_DIM];
__device__ float d_part[(size_t)T_TOK * TOPK * H_DIM];

// ---------------- helpers ----------------
#define SWZ(o) ((o) ^ (((o) >> 3) & 0x70))

__device__ __forceinline__ uint32_t smem_u32(const void* p) {
    uint32_t a;
    asm("{ .reg .u64 t; cvta.to.shared.u64 t, %1; cvt.u32.u64 %0, t; }" : "=r"(a) : "l"(p));
    return a;
}

#define CP16(sa, ga, sz) \
    asm volatile("cp.async.cg.shared.global [%0], [%1], 16, %2;" \
                 :: "r"(sa), "l"(ga), "r"(sz) : "memory")
#define CP_COMMIT() asm volatile("cp.async.commit_group;" ::: "memory")
#define CP_WAIT(n)  asm volatile("cp.async.wait_group %0;" :: "n"(n) : "memory")

#define LDM4(r0, r1, r2, r3, a) \
    asm volatile("ldmatrix.sync.aligned.m8n8.x4.shared.b16 {%0,%1,%2,%3}, [%4];" \
                 : "=r"(r0), "=r"(r1), "=r"(r2), "=r"(r3) : "r"(a))

#define MMA(d, a, b) \
    asm volatile("mma.sync.aligned.m16n8k16.row.col.f32.bf16.bf16.f32 " \
                 "{%0,%1,%2,%3}, {%4,%5,%6,%7}, {%8,%9}, {%0,%1,%2,%3};" \
                 : "+f"((d)[0]), "+f"((d)[1]), "+f"((d)[2]), "+f"((d)[3]) \
                 : "r"((a)[0]), "r"((a)[1]), "r"((a)[2]), "r"((a)[3]), \
                   "r"((b)[0]), "r"((b)[1]))

// stage layouts: 128B rows carrying [hi 64B | lo 64B] for 32 k-elements
// gemm1: X 64x128B (8K) | W1 8K | W3 8K = 24K/stage, 4 stages
#define X1O  0
#define W1O  8192
#define W3O  16384
#define S1   24576
#define SMEM1 (4 * S1)
// gemm2: A 128x128B (16K) | W 8K = 24K/stage, 4 stages
#define A2O  0
#define W2O  16384
#define S2   24576
#define SMEM2 (4 * S2)
#define NPAD 68

// ---------------- init ----------------
__global__ void init_k() { if (threadIdx.x < N_EXP) d_cnt[threadIdx.x] = 0; }

// ---------------- fp32 -> interleaved bf16 hi/lo ----------------
template <int RL>
__device__ __forceinline__ void split_store_i(__nv_bfloat16* dst, size_t g4, float4 v) {
    const size_t row = g4 / RL;
    const int g = (int)(g4 % RL);
    const size_t base = row * (size_t)(2 * RL) + ((g >> 5) << 6) + (g & 31);
    __nv_bfloat16 h0 = __float2bfloat16(v.x), h1 = __float2bfloat16(v.y);
    __nv_bfloat16 h2 = __float2bfloat16(v.z), h3 = __float2bfloat16(v.w);
    __nv_bfloat16 l0 = __float2bfloat16(v.x - __bfloat162float(h0));
    __nv_bfloat16 l1 = __float2bfloat16(v.y - __bfloat162float(h1));
    __nv_bfloat16 l2 = __float2bfloat16(v.z - __bfloat162float(h2));
    __nv_bfloat16 l3 = __float2bfloat16(v.w - __bfloat162float(h3));
    *(__nv_bfloat162*)(dst + base + 0)  = __halves2bfloat162(h0, h1);
    *(__nv_bfloat162*)(dst + base + 2)  = __halves2bfloat162(h2, h3);
    *(__nv_bfloat162*)(dst + base + 32) = __halves2bfloat162(l0, l1);
    *(__nv_bfloat162*)(dst + base + 34) = __halves2bfloat162(l2, l3);
}

// ---------------- fused prep: conv w1/w3 + conv x + router ----------------
#define PREP_W_BLOCKS 2048
#define PREP_X_BLOCKS 256
__global__ __launch_bounds__(256) void prep_k(const float* __restrict__ x,
                                              const float* __restrict__ gw,
                                              const float* __restrict__ w1,
                                              const float* __restrict__ w3) {
    const int b = blockIdx.x;
    const int tid = threadIdx.x;

    if (b < PREP_W_BLOCKS) {
        const int n = N_EXP * I_DIM * H_DIM / 4;
        for (int i = b * 256 + tid; i < n; i += PREP_W_BLOCKS * 256) {
            split_store_i<H_DIM>(d_w1i, (size_t)i * 4, ((const float4*)w1)[i]);
            split_store_i<H_DIM>(d_w3i, (size_t)i * 4, ((const float4*)w3)[i]);
        }
        return;
    }
    if (b < PREP_W_BLOCKS + PREP_X_BLOCKS) {
        const int b2 = b - PREP_W_BLOCKS;
        const int n = T_TOK * H_DIM / 4;
        for (int i = b2 * 256 + tid; i < n; i += PREP_X_BLOCKS * 256)
            split_store_i<H_DIM>(d_xi, (size_t)i * 4, ((const float4*)x)[i]);
        return;
    }

    // router: one token per block
    __shared__ float xs[H_DIM];
    __shared__ float lg[N_EXP];
    const int t = b - (PREP_W_BLOCKS + PREP_X_BLOCKS);
    const float* xr = x + (size_t)t * H_DIM;
    for (int i = tid; i < H_DIM / 4; i += 256)
        ((float4*)xs)[i] = ((const float4*)xr)[i];
    __syncthreads();

    const int w = tid >> 5, lane = tid & 31;
    #pragma unroll
    for (int j = 0; j < 2; j++) {
        const int e = w * 2 + j;
        const float* g = gw + (size_t)e * H_DIM;
        float s = 0.f;
        for (int h = lane; h < H_DIM; h += 32) s += xs[h] * g[h];
        #pragma unroll
        for (int o = 16; o; o >>= 1) s += __shfl_xor_sync(0xffffffffu, s, o);
        if (lane == 0) lg[e] = s;
    }
    __syncthreads();

    if (tid == 0) {
        int sel[TOPK]; float sl[TOPK];
        unsigned used = 0;
        for (int k = 0; k < TOPK; k++) {
            float best = -1e30f; int bi = 0;
            for (int e = 0; e < N_EXP; e++)
                if (!((used >> e) & 1u) && lg[e] > best) { best = lg[e]; bi = e; }
            used |= 1u << bi; sel[k] = bi; sl[k] = best;
        }
        float m = sl[0], ex[TOPK], sum = 0.f;
        for (int k = 0; k < TOPK; k++) { ex[k] = expf(sl[k] - m); sum += ex[k]; }
        float inv = 1.f / sum;
        for (int k = 0; k < TOPK; k++) {
            int e = sel[k];
            int pos = atomicAdd(&d_cnt[e], 1);
            d_tok [e * CAP + pos] = t;
            d_slot[e * CAP + pos] = k;
            d_wt  [e * CAP + pos] = ex[k] * inv;
        }
    }
}

// ---------------- gemm1: act = silu(X W1^T) * (X W3^T) ----------------
// CTA 64x64, 256 thr; warps 0-3 -> W1, warps 4-7 -> W3 (2x2 each).
// KC=32, 4-stage ring, one __syncthreads per chunk.
// blockIdx.z == N_EXP: co-scheduled w2 conversion (pure memory).
__global__ __launch_bounds__(256, 2) void gemm1_t(const float* __restrict__ w2) {
    const int tid = threadIdx.x;
    if (blockIdx.z == N_EXP) {
        const int bid = blockIdx.x * 8 + blockIdx.y;       // 0..255
        const int n = N_EXP * H_DIM * I_DIM / 4;
        for (int i = bid * 256 + tid; i < n; i += 256 * 256)
            split_store_i<I_DIM>(d_w2i, (size_t)i * 4, ((const float4*)w2)[i]);
        return;
    }

    extern __shared__ char smem[];
    const int e = blockIdx.z, m0 = blockIdx.x * 64, n0 = blockIdx.y * 64;
    const int cnt = d_cnt[e];
    if (m0 >= cnt) return;

    const uint32_t sb = smem_u32(smem);
    const int wid = tid >> 5, lid = tid & 31;
    const int wg = wid >> 2, wl = wid & 3;
    const int wm = wl & 1, wn = wl >> 1;   // 2x2 warp grid per group

    __shared__ int toks[64];
    if (tid < 64) toks[tid] = (m0 + tid < cnt) ? d_tok[e * CAP + m0 + tid] : -1;
    __syncthreads();

    const __nv_bfloat16* w1e = d_w1i + ((size_t)e * I_DIM + n0) * (2 * H_DIM);
    const __nv_bfloat16* w3e = d_w3i + ((size_t)e * I_DIM + n0) * (2 * H_DIM);

    // per-thread load coords: 8 threads per 128B row, rows lr and lr+32
    const int lr = tid >> 3, ls = tid & 7;
    const int t0 = toks[lr], t1 = toks[lr + 32];
    const unsigned xp0 = (t0 >= 0) ? 16u : 0u;
    const unsigned xp1 = (t1 >= 0) ? 16u : 0u;
    const __nv_bfloat16* xsrc0 = d_xi + (size_t)(t0 < 0 ? 0 : t0) * (2 * H_DIM) + ls * 8;
    const __nv_bfloat16* xsrc1 = d_xi + (size_t)(t1 < 0 ? 0 : t1) * (2 * H_DIM) + ls * 8;
    const size_t wstep = (size_t)32 * (2 * H_DIM);
    const __nv_bfloat16* w1src = w1e + (size_t)lr * (2 * H_DIM) + ls * 8;
    const __nv_bfloat16* w3src = w3e + (size_t)lr * (2 * H_DIM) + ls * 8;
    const uint32_t sdst = SWZ(lr * 128 + ls * 16);

    auto load1 = [&](int c) {
        const uint32_t bo = sb + (c & 3) * S1;
        const size_t ko = (size_t)c * 64;
        CP16(bo + X1O + sdst,        xsrc0 + ko,         xp0);
        CP16(bo + X1O + sdst + 4096, xsrc1 + ko,         xp1);
        CP16(bo + W1O + sdst,        w1src + ko,         16u);
        CP16(bo + W1O + sdst + 4096, w1src + ko + wstep, 16u);
        CP16(bo + W3O + sdst,        w3src + ko,         16u);
        CP16(bo + W3O + sdst + 4096, w3src + ko + wstep, 16u);
        CP_COMMIT();
    };

    float acc[2][4][4] = {};
    const int ar = lid & 15, ac = (lid >> 4) * 8;
    const int bq = lid >> 3, brr = lid & 7;
    const int bn = (bq >> 1) * 8 + brr, bk = (bq & 1) * 8;
    const uint32_t wB = wg ? W3O : W1O;

    const int NCH = H_DIM / 32;   // 32
    load1(0); load1(1);
    for (int c = 0; c < NCH; c++) {
        if (c + 2 < NCH) { load1(c + 2); CP_WAIT(2); }
        else if (c + 1 < NCH) { CP_WAIT(1); }
        else { CP_WAIT(0); }
        __syncthreads();
        const uint32_t bo = sb + (c & 3) * S1;

        #pragma unroll
        for (int ks = 0; ks < 2; ks++) {
            const int k = ks * 16;
            uint32_t ah[2][4], al[2][4];
            #pragma unroll
            for (int mi = 0; mi < 2; mi++) {
                const int row = wm * 32 + mi * 16 + ar;
                LDM4(ah[mi][0], ah[mi][1], ah[mi][2], ah[mi][3],
                     bo + X1O + SWZ(row * 128 + (k + ac) * 2));
                LDM4(al[mi][0], al[mi][1], al[mi][2], al[mi][3],
                     bo + X1O + SWZ(row * 128 + 64 + (k + ac) * 2));
            }
            #pragma unroll
            for (int nh = 0; nh < 2; nh++) {
                const int row = wn * 32 + nh * 16 + bn;
                uint32_t bh[4], bl[4];
                LDM4(bh[0], bh[1], bh[2], bh[3], bo + wB + SWZ(row * 128 + (k + bk) * 2));
                LDM4(bl[0], bl[1], bl[2], bl[3], bo + wB + SWZ(row * 128 + 64 + (k + bk) * 2));
                #pragma unroll
                for (int mi = 0; mi < 2; mi++)
                    #pragma unroll
                    for (int j = 0; j < 2; j++) {
                        const int nj = 2 * nh + j;
                        MMA(acc[mi][nj], ah[mi], bh + 2 * j);
                        MMA(acc[mi][nj], ah[mi], bl + 2 * j);
                        MMA(acc[mi][nj], al[mi], bh + 2 * j);
                    }
            }
        }
    }
    __syncthreads();

    // exchange: w3-group stores acc to smem; w1-group fuses silu*mul, writes act (interleaved)
    float* xch = (float*)smem;
    const int g = lid >> 2, tg = lid & 3;
    if (wg == 1) {
        #pragma unroll
        for (int mi = 0; mi < 2; mi++)
            #pragma unroll
            for (int sub = 0; sub < 2; sub++) {
                const int r = wm * 32 + mi * 16 + sub * 8 + g;
                #pragma unroll
                for (int nj = 0; nj < 4; nj++) {
                    const int cc = wn * 32 + nj * 8 + 2 * tg;
                    *(float2*)&xch[r * NPAD + cc] =
                        make_float2(acc[mi][nj][2 * sub], acc[mi][nj][2 * sub + 1]);
                }
            }
    }
    __syncthreads();
    if (wg == 0) {
        #pragma unroll
        for (int mi = 0; mi < 2; mi++)
            #pragma unroll
            for (int sub = 0; sub < 2; sub++) {
                const int mr = wm * 32 + mi * 16 + sub * 8 + g;
                const int m = m0 + mr;
                if (m >= cnt) continue;
                const size_t arow = ((size_t)e * CAP + m) * (2 * I_DIM);
                #pragma unroll
                for (int nj = 0; nj < 4; nj++) {
                    const int cc = wn * 32 + nj * 8 + 2 * tg;
                    float2 g3 = *(float2*)&xch[mr * NPAD + cc];
                    float h0 = acc[mi][nj][2 * sub], h1 = acc[mi][nj][2 * sub + 1];
                    float v0 = (h0 / (1.f + expf(-h0))) * g3.x;
                    float v1 = (h1 / (1.f + expf(-h1))) * g3.y;
                    __nv_bfloat16 a0 = __float2bfloat16(v0), a1 = __float2bfloat16(v1);
                    __nv_bfloat16 b0 = __float2bfloat16(v0 - __bfloat162float(a0));
                    __nv_bfloat16 b1 = __float2bfloat16(v1 - __bfloat162float(a1));
                    const int gg = n0 + cc;
                    const size_t base = arow + ((gg >> 5) << 6) + (gg & 31);
                    *(__nv_bfloat162*)(d_ai + base)      = __halves2bfloat162(a0, a1);
                    *(__nv_bfloat162*)(d_ai + base + 32) = __halves2bfloat162(b0, b1);
                }
            }
    }
}

// ---------------- gemm2: part[t][slot] = w * (act W2^T), CTA 128x64 ----------------
__global__ __launch_bounds__(256, 2) void gemm2_t() {
    extern __shared__ char smem[];
    const int e = blockIdx.z, m0 = blockIdx.x * 128, n0 = blockIdx.y * 64;  // n over H
    const int cnt = d_cnt[e];
    if (m0 >= cnt) return;

    const uint32_t sb = smem_u32(smem);
    const int tid = threadIdx.x, wid = tid >> 5, lid = tid & 31;
    const int wm = wid & 3, wn = wid >> 2;   // 4x2 warp grid

    __shared__ int   toks[128];
    __shared__ int   slots[128];
    __shared__ float wts[128];
    if (tid < 128) {
        const int m = m0 + tid;
        const bool v = (m < cnt);
        toks [tid] = v ? d_tok [e * CAP + m] : 0;
        slots[tid] = v ? d_slot[e * CAP + m] : 0;
        wts  [tid] = v ? d_wt  [e * CAP + m] : 0.f;
    }
    __syncthreads();

    const __nv_bfloat16* w2e = d_w2i + ((size_t)e * H_DIM + n0) * (2 * I_DIM);
    const size_t abase = ((size_t)e * CAP + m0) * (2 * I_DIM);

    const int lr = tid >> 3, ls = tid & 7;
    const unsigned ap0 = (m0 + lr       < cnt) ? 16u : 0u;
    const unsigned ap1 = (m0 + lr + 32  < cnt) ? 16u : 0u;
    const unsigned ap2 = (m0 + lr + 64  < cnt) ? 16u : 0u;
    const unsigned ap3 = (m0 + lr + 96  < cnt) ? 16u : 0u;
    const __nv_bfloat16* asrc = d_ai + abase + (size_t)lr * (2 * I_DIM) + ls * 8;
    const __nv_bfloat16* wsrc = w2e + (size_t)lr * (2 * I_DIM) + ls * 8;
    const uint32_t sd = SWZ(lr * 128 + ls * 16);
    const size_t astep = (size_t)32 * (2 * I_DIM);

    auto load2 = [&](int c) {
        const uint32_t bo = sb + (c & 3) * S2;
        const size_t ko = (size_t)c * 64;
        CP16(bo + A2O + sd,          asrc + ko,             ap0);
        CP16(bo + A2O + sd + 4096,   asrc + ko + astep,     ap1);
        CP16(bo + A2O + sd + 8192,   asrc + ko + 2 * astep, ap2);
        CP16(bo + A2O + sd + 12288,  asrc + ko + 3 * astep, ap3);
        CP16(bo + W2O + sd, wsrc + ko, 16u);
        CP16(bo + W2O + sd + 4096, wsrc + ko + astep, 16u);
        CP_COMMIT();
    };

    float acc[2][4][4] = {};
    const int ar = lid & 15, ac = (lid >> 4) * 8;
    const int bq = lid >> 3, brr = lid & 7;
    const int bn = (bq >> 1) * 8 + brr, bk = (bq & 1) * 8;

    const int NCH = I_DIM / 32;   // 16
    load2(0); load2(1);
    for (int c = 0; c < NCH; c++) {
        if (c + 2 < NCH) { load2(c + 2); CP_WAIT(2); }
        else if (c + 1 < NCH) { CP_WAIT(1); }
        else { CP_WAIT(0); }
        __syncthreads();
        const uint32_t bo = sb + (c & 3) * S2;

        #pragma unroll
        for (int ks = 0; ks < 2; ks++) {
            const int k = ks * 16;
            uint32_t ah[2][4], al[2][4];
            #pragma unroll
            for (int mi = 0; mi < 2; mi++) {
                const int row = wm * 32 + mi * 16 + ar;
                LDM4(ah[mi][0], ah[mi][1], ah[mi][2], ah[mi][3],
                     bo + A2O + SWZ(row * 128 + (k + ac) * 2));
                LDM4(al[mi][0], al[mi][1], al[mi][2], al[mi][3],
                     bo + A2O + SWZ(row * 128 + 64 + (k + ac) * 2));
            }
            #pragma unroll
            for (int nh = 0; nh < 2; nh++) {
                const int row = wn * 32 + nh * 16 + bn;
                uint32_t bh[4], bl[4];
                LDM4(bh[0], bh[1], bh[2], bh[3], bo + W2O + SWZ(row * 128 + (k + bk) * 2));
                LDM4(bl[0], bl[1], bl[2], bl[3], bo + W2O + SWZ(row * 128 + 64 + (k + bk) * 2));
                #pragma unroll
                for (int mi = 0; mi < 2; mi++)
                    #pragma unroll
                    for (int j = 0; j < 2; j++) {
                        const int nj = 2 * nh + j;
                        MMA(acc[mi][nj], ah[mi], bh + 2 * j);
                        MMA(acc[mi][nj], ah[mi], bl + 2 * j);
                        MMA(acc[mi][nj], al[mi], bh + 2 * j);
                    }
            }
        }
    }

    const int g = lid >> 2, tg = lid & 3;
    #pragma unroll
    for (int mi = 0; mi < 2; mi++)
        #pragma unroll
        for (int sub = 0; sub < 2; sub++) {
            const int mrow = wm * 32 + mi * 16 + sub * 8 + g;
            if (m0 + mrow >= cnt) continue;
            const int t = toks[mrow], sk = slots[mrow];
            const float wv = wts[mrow];
            const size_t pbase = ((size_t)t * TOPK + sk) * H_DIM + n0 + wn * 32;
            #pragma unroll
            for (int nj = 0; nj < 4; nj++) {
                float2 o;
                o.x = wv * acc[mi][nj][2 * sub];
                o.y = wv * acc[mi][nj][2 * sub + 1];
                *(float2*)(d_part + pbase + nj * 8 + 2 * tg) = o;
            }
        }
}

// ---------------- combine ----------------
__global__ __launch_bounds__(256) void combine_k(float* __restrict__ out) {
    const int idx = blockIdx.x * blockDim.x + threadIdx.x;
    const int t = idx >> 8, c4 = idx & 255;
    const float4* p = (const float4*)d_part + (size_t)t * TOPK * 256 + c4;
    float4 a = p[0], b = p[256], c = p[512], d = p[768];
    float4 o;
    o.x = a.x + b.x + c.x + d.x;
    o.y = a.y + b.y + c.y + d.y;
    o.z = a.z + b.z + c.z + d.z;
    o.w = a.w + b.w + c.w + d.w;
    ((float4*)out)[idx] = o;
}

// ---------------- launch ----------------
extern "C" void kernel_launch(void* const* d_in, const int* in_sizes, int n_in,
                              void* d_out, int out_size) {
    const float* x  = (const float*)d_in[0];
    const float* gw = (const float*)d_in[1];
    const float* w1 = (const float*)d_in[2];
    const float* w3 = (const float*)d_in[3];
    const float* w2 = (const float*)d_in[4];
    float* out = (float*)d_out;

    cudaFuncSetAttribute(gemm1_t, cudaFuncAttributeMaxDynamicSharedMemorySize, SMEM1);
    cudaFuncSetAttribute(gemm2_t, cudaFuncAttributeMaxDynamicSharedMemorySize, SMEM2);

    init_k<<<1, 32>>>();
    prep_k<<<PREP_W_BLOCKS + PREP_X_BLOCKS + T_TOK, 256>>>(x, gw, w1, w3);
    gemm1_t<<<dim3(CAP / 64, I_DIM / 64, N_EXP + 1), 256, SMEM1>>>(w2);
    gemm2_t<<<dim3(CAP / 128, H_DIM / 64, N_EXP), 256, SMEM2>>>();
    combine_k<<<T_TOK, 256>>>(out);
}

// round 16
// speedup vs baseline: 1.6160x; 1.0414x over previous
#include <cuda_runtime.h>
#include <cuda_bf16.h>
#include <math.h>
#include <stdint.h>

#define T_TOK 2048
#define H_DIM 1024
#define I_DIM 512
#define N_EXP 16
#define TOPK  4
#define CAP   2048

// interleaved hi/lo layout: logical row of R elements -> 2R bf16,
// element g: hi at row*2R + (g>>5)*64 + (g&31), lo at +32.
__device__ int   d_cnt[N_EXP];
__device__ int   d_tok[N_EXP * CAP];
__device__ int   d_slot[N_EXP * CAP];
__device__ float d_wt [N_EXP * CAP];
__device__ __nv_bfloat16 d_xi [(size_t)T_TOK * 2 * H_DIM];
__device__ __nv_bfloat16 d_w1i[(size_t)N_EXP * I_DIM * 2 * H_DIM];
__device__ __nv_bfloat16 d_w3i[(size_t)N_EXP * I_DIM * 2 * H_DIM];
__device__ __nv_bfloat16 d_w2i[(size_t)N_EXP * H_DIM * 2 * I_DIM];
__device__ __nv_bfloat16 d_ai [(size_t)N_EXP * CAP * 2 * I_DIM];
__device__ float d_part[(size_t)T_TOK * TOPK * H_DIM];

// ---------------- helpers ----------------
#define SWZ(o) ((o) ^ (((o) >> 3) & 0x70))

__device__ __forceinline__ uint32_t smem_u32(const void* p) {
    uint32_t a;
    asm("{ .reg .u64 t; cvta.to.shared.u64 t, %1; cvt.u32.u64 %0, t; }" : "=r"(a) : "l"(p));
    return a;
}

#define CP16(sa, ga, sz) \
    asm volatile("cp.async.cg.shared.global [%0], [%1], 16, %2;" \
                 :: "r"(sa), "l"(ga), "r"(sz) : "memory")
#define CP_COMMIT() asm volatile("cp.async.commit_group;" ::: "memory")
#define CP_WAIT(n)  asm volatile("cp.async.wait_group %0;" :: "n"(n) : "memory")

#define LDM4(r0, r1, r2, r3, a) \
    asm volatile("ldmatrix.sync.aligned.m8n8.x4.shared.b16 {%0,%1,%2,%3}, [%4];" \
                 : "=r"(r0), "=r"(r1), "=r"(r2), "=r"(r3) : "r"(a))

#define MMA(d, a, b) \
    asm volatile("mma.sync.aligned.m16n8k16.row.col.f32.bf16.bf16.f32 " \
                 "{%0,%1,%2,%3}, {%4,%5,%6,%7}, {%8,%9}, {%0,%1,%2,%3};" \
                 : "+f"((d)[0]), "+f"((d)[1]), "+f"((d)[2]), "+f"((d)[3]) \
                 : "r"((a)[0]), "r"((a)[1]), "r"((a)[2]), "r"((a)[3]), \
                   "r"((b)[0]), "r"((b)[1]))

// stage layouts: 128B rows carrying [hi 64B | lo 64B] for 32 k-elements
// gemm1 (CTA 64x64, 128 thr): X 8K | W1 8K | W3 8K = 24K/stage, 2 stages
#define X1O  0
#define W1O  8192
#define W3O  16384
#define S1   24576
#define SMEM1 (2 * S1)
// gemm2 (CTA 64x64, 128 thr): A 8K | W 8K = 16K/stage, 2 stages
#define A2O  0
#define W2O  8192
#define S2   16384
#define SMEM2 (2 * S2)

// ---------------- init ----------------
__global__ void init_k() { if (threadIdx.x < N_EXP) d_cnt[threadIdx.x] = 0; }

// ---------------- fp32 -> interleaved bf16 hi/lo ----------------
template <int RL>
__device__ __forceinline__ void split_store_i(__nv_bfloat16* dst, size_t g4, float4 v) {
    const size_t row = g4 / RL;
    const int g = (int)(g4 % RL);
    const size_t base = row * (size_t)(2 * RL) + ((g >> 5) << 6) + (g & 31);
    __nv_bfloat16 h0 = __float2bfloat16(v.x), h1 = __float2bfloat16(v.y);
    __nv_bfloat16 h2 = __float2bfloat16(v.z), h3 = __float2bfloat16(v.w);
    __nv_bfloat16 l0 = __float2bfloat16(v.x - __bfloat162float(h0));
    __nv_bfloat16 l1 = __float2bfloat16(v.y - __bfloat162float(h1));
    __nv_bfloat16 l2 = __float2bfloat16(v.z - __bfloat162float(h2));
    __nv_bfloat16 l3 = __float2bfloat16(v.w - __bfloat162float(h3));
    *(__nv_bfloat162*)(dst + base + 0)  = __halves2bfloat162(h0, h1);
    *(__nv_bfloat162*)(dst + base + 2)  = __halves2bfloat162(h2, h3);
    *(__nv_bfloat162*)(dst + base + 32) = __halves2bfloat162(l0, l1);
    *(__nv_bfloat162*)(dst + base + 34) = __halves2bfloat162(l2, l3);
}

// ---------------- fused prep: conv w1/w3 + conv x + router ----------------
#define PREP_W_BLOCKS 2048
#define PREP_X_BLOCKS 256
__global__ __launch_bounds__(256) void prep_k(const float* __restrict__ x,
                                              const float* __restrict__ gw,
                                              const float* __restrict__ w1,
                                              const float* __restrict__ w3) {
    const int b = blockIdx.x;
    const int tid = threadIdx.x;

    if (b < PREP_W_BLOCKS) {
        const int n = N_EXP * I_DIM * H_DIM / 4;
        for (int i = b * 256 + tid; i < n; i += PREP_W_BLOCKS * 256) {
            split_store_i<H_DIM>(d_w1i, (size_t)i * 4, ((const float4*)w1)[i]);
            split_store_i<H_DIM>(d_w3i, (size_t)i * 4, ((const float4*)w3)[i]);
        }
        return;
    }
    if (b < PREP_W_BLOCKS + PREP_X_BLOCKS) {
        const int b2 = b - PREP_W_BLOCKS;
        const int n = T_TOK * H_DIM / 4;
        for (int i = b2 * 256 + tid; i < n; i += PREP_X_BLOCKS * 256)
            split_store_i<H_DIM>(d_xi, (size_t)i * 4, ((const float4*)x)[i]);
        return;
    }

    // router: one token per block
    __shared__ float xs[H_DIM];
    __shared__ float lg[N_EXP];
    const int t = b - (PREP_W_BLOCKS + PREP_X_BLOCKS);
    const float* xr = x + (size_t)t * H_DIM;
    for (int i = tid; i < H_DIM / 4; i += 256)
        ((float4*)xs)[i] = ((const float4*)xr)[i];
    __syncthreads();

    const int w = tid >> 5, lane = tid & 31;
    #pragma unroll
    for (int j = 0; j < 2; j++) {
        const int e = w * 2 + j;
        const float* g = gw + (size_t)e * H_DIM;
        float s = 0.f;
        for (int h = lane; h < H_DIM; h += 32) s += xs[h] * g[h];
        #pragma unroll
        for (int o = 16; o; o >>= 1) s += __shfl_xor_sync(0xffffffffu, s, o);
        if (lane == 0) lg[e] = s;
    }
    __syncthreads();

    if (tid == 0) {
        int sel[TOPK]; float sl[TOPK];
        unsigned used = 0;
        for (int k = 0; k < TOPK; k++) {
            float best = -1e30f; int bi = 0;
            for (int e = 0; e < N_EXP; e++)
                if (!((used >> e) & 1u) && lg[e] > best) { best = lg[e]; bi = e; }
            used |= 1u << bi; sel[k] = bi; sl[k] = best;
        }
        float m = sl[0], ex[TOPK], sum = 0.f;
        for (int k = 0; k < TOPK; k++) { ex[k] = expf(sl[k] - m); sum += ex[k]; }
        float inv = 1.f / sum;
        for (int k = 0; k < TOPK; k++) {
            int e = sel[k];
            int pos = atomicAdd(&d_cnt[e], 1);
            d_tok [e * CAP + pos] = t;
            d_slot[e * CAP + pos] = k;
            d_wt  [e * CAP + pos] = ex[k] * inv;
        }
    }
}

// ---------------- gemm1: act = silu(X W1^T) * (X W3^T) ----------------
// 128 thr, CTA 64x64; 4 warps (2x2), each computes BOTH acc1 and acc3 for
// its full 32x32 tile (nh loop over two 16-row B groups). KC=32, 2-stage.
// blockIdx.z == N_EXP: co-scheduled w2 conversion (pure memory).
__global__ __launch_bounds__(128, 3) void gemm1_t(const float* __restrict__ w2) {
    const int tid = threadIdx.x;
    if (blockIdx.z == N_EXP) {
        const int bid = blockIdx.x * 8 + blockIdx.y;       // 0..255
        const int n = N_EXP * H_DIM * I_DIM / 4;
        for (int i = bid * 128 + tid; i < n; i += 256 * 128)
            split_store_i<I_DIM>(d_w2i, (size_t)i * 4, ((const float4*)w2)[i]);
        return;
    }

    extern __shared__ char smem[];
    const int e = blockIdx.z, m0 = blockIdx.x * 64, n0 = blockIdx.y * 64;
    const int cnt = d_cnt[e];
    if (m0 >= cnt) return;

    const uint32_t sb = smem_u32(smem);
    const int wid = tid >> 5, lid = tid & 31;
    const int wm = wid & 1, wn = wid >> 1;   // 2x2 warp grid

    __shared__ int toks[64];
    if (tid < 64) toks[tid] = (m0 + tid < cnt) ? d_tok[e * CAP + m0 + tid] : -1;
    __syncthreads();

    const __nv_bfloat16* w1e = d_w1i + ((size_t)e * I_DIM + n0) * (2 * H_DIM);
    const __nv_bfloat16* w3e = d_w3i + ((size_t)e * I_DIM + n0) * (2 * H_DIM);

    // loader coords: 8 threads per 128B row; rows lr+16j, j=0..3
    const int lr = tid >> 3, ls = tid & 7;
    unsigned xp[4]; const __nv_bfloat16* xs4[4];
    #pragma unroll
    for (int j = 0; j < 4; j++) {
        const int t = toks[lr + 16 * j];
        xp[j] = (t >= 0) ? 16u : 0u;
        xs4[j] = d_xi + (size_t)(t < 0 ? 0 : t) * (2 * H_DIM) + ls * 8;
    }
    const size_t wstep = (size_t)16 * (2 * H_DIM);
    const __nv_bfloat16* w1src = w1e + (size_t)lr * (2 * H_DIM) + ls * 8;
    const __nv_bfloat16* w3src = w3e + (size_t)lr * (2 * H_DIM) + ls * 8;
    const uint32_t sd0 = SWZ(lr * 128 + ls * 16);   // rows lr+16j => +j*2048

    auto load1 = [&](int c) {
        const uint32_t bo = sb + (c & 1) * S1;
        const size_t ko = (size_t)c * 64;
        #pragma unroll
        for (int j = 0; j < 4; j++) {
            CP16(bo + X1O + sd0 + j * 2048, xs4[j] + ko, xp[j]);
            CP16(bo + W1O + sd0 + j * 2048, w1src + j * wstep + ko, 16u);
            CP16(bo + W3O + sd0 + j * 2048, w3src + j * wstep + ko, 16u);
        }
        CP_COMMIT();
    };

    float acc1[2][4][4] = {}, acc3[2][4][4] = {};
    const int ar = lid & 15, ac = (lid >> 4) * 8;
    const int bq = lid >> 3, brr = lid & 7;
    const int bn = (bq >> 1) * 8 + brr, bk = (bq & 1) * 8;

    load1(0);
    const int NCH = H_DIM / 32;   // 32
    for (int c = 0; c < NCH; c++) {
        if (c + 1 < NCH) { load1(c + 1); CP_WAIT(1); }
        else CP_WAIT(0);
        __syncthreads();
        const uint32_t bo = sb + (c & 1) * S1;

        #pragma unroll
        for (int ks = 0; ks < 2; ks++) {
            const int k = ks * 16;
            uint32_t ah[2][4], al[2][4];
            #pragma unroll
            for (int mi = 0; mi < 2; mi++) {
                const int row = wm * 32 + mi * 16 + ar;
                LDM4(ah[mi][0], ah[mi][1], ah[mi][2], ah[mi][3],
                     bo + X1O + SWZ(row * 128 + (k + ac) * 2));
                LDM4(al[mi][0], al[mi][1], al[mi][2], al[mi][3],
                     bo + X1O + SWZ(row * 128 + 64 + (k + ac) * 2));
            }
            #pragma unroll
            for (int nh = 0; nh < 2; nh++) {
                const int row = wn * 32 + nh * 16 + bn;
                uint32_t b1h[4], b1l[4], b3h[4], b3l[4];
                LDM4(b1h[0], b1h[1], b1h[2], b1h[3], bo + W1O + SWZ(row * 128 + (k + bk) * 2));
                LDM4(b1l[0], b1l[1], b1l[2], b1l[3], bo + W1O + SWZ(row * 128 + 64 + (k + bk) * 2));
                LDM4(b3h[0], b3h[1], b3h[2], b3h[3], bo + W3O + SWZ(row * 128 + (k + bk) * 2));
                LDM4(b3l[0], b3l[1], b3l[2], b3l[3], bo + W3O + SWZ(row * 128 + 64 + (k + bk) * 2));
                #pragma unroll
                for (int mi = 0; mi < 2; mi++)
                    #pragma unroll
                    for (int j = 0; j < 2; j++) {
                        const int nj = 2 * nh + j;
                        MMA(acc1[mi][nj], ah[mi], b1h + 2 * j);
                        MMA(acc1[mi][nj], ah[mi], b1l + 2 * j);
                        MMA(acc1[mi][nj], al[mi], b1h + 2 * j);
                        MMA(acc3[mi][nj], ah[mi], b3h + 2 * j);
                        MMA(acc3[mi][nj], ah[mi], b3l + 2 * j);
                        MMA(acc3[mi][nj], al[mi], b3h + 2 * j);
                    }
            }
        }
        __syncthreads();
    }

    // epilogue: silu(acc1)*acc3 in-warp, write interleaved act
    const int g = lid >> 2, tg = lid & 3;
    #pragma unroll
    for (int mi = 0; mi < 2; mi++)
        #pragma unroll
        for (int sub = 0; sub < 2; sub++) {
            const int mr = wm * 32 + mi * 16 + sub * 8 + g;
            const int m = m0 + mr;
            if (m >= cnt) continue;
            const size_t arow = ((size_t)e * CAP + m) * (2 * I_DIM);
            #pragma unroll
            for (int nj = 0; nj < 4; nj++) {
                const int cc = wn * 32 + nj * 8 + 2 * tg;
                float h0 = acc1[mi][nj][2 * sub], h1 = acc1[mi][nj][2 * sub + 1];
                float g0 = acc3[mi][nj][2 * sub], g1 = acc3[mi][nj][2 * sub + 1];
                float v0 = (h0 / (1.f + expf(-h0))) * g0;
                float v1 = (h1 / (1.f + expf(-h1))) * g1;
                __nv_bfloat16 a0 = __float2bfloat16(v0), a1 = __float2bfloat16(v1);
                __nv_bfloat16 b0 = __float2bfloat16(v0 - __bfloat162float(a0));
                __nv_bfloat16 b1 = __float2bfloat16(v1 - __bfloat162float(a1));
                const int gg = n0 + cc;
                const size_t base = arow + ((gg >> 5) << 6) + (gg & 31);
                *(__nv_bfloat162*)(d_ai + base)      = __halves2bfloat162(a0, a1);
                *(__nv_bfloat162*)(d_ai + base + 32) = __halves2bfloat162(b0, b1);
            }
        }
}

// ---------------- gemm2: part[t][slot] = w * (act W2^T), CTA 64x64, 128 thr ----------------
__global__ __launch_bounds__(128, 4) void gemm2_t() {
    extern __shared__ char smem[];
    const int e = blockIdx.z, m0 = blockIdx.x * 64, n0 = blockIdx.y * 64;  // n over H
    const int cnt = d_cnt[e];
    if (m0 >= cnt) return;

    const uint32_t sb = smem_u32(smem);
    const int tid = threadIdx.x, wid = tid >> 5, lid = tid & 31;
    const int wm = wid & 1, wn = wid >> 1;   // 2x2 warp grid

    __shared__ int   toks[64];
    __shared__ int   slots[64];
    __shared__ float wts[64];
    if (tid < 64) {
        const int m = m0 + tid;
        const bool v = (m < cnt);
        toks [tid] = v ? d_tok [e * CAP + m] : 0;
        slots[tid] = v ? d_slot[e * CAP + m] : 0;
        wts  [tid] = v ? d_wt  [e * CAP + m] : 0.f;
    }
    __syncthreads();

    const __nv_bfloat16* w2e = d_w2i + ((size_t)e * H_DIM + n0) * (2 * I_DIM);
    const size_t abase = ((size_t)e * CAP + m0) * (2 * I_DIM);

    const int lr = tid >> 3, ls = tid & 7;
    unsigned ap[4];
    #pragma unroll
    for (int j = 0; j < 4; j++) ap[j] = (m0 + lr + 16 * j < cnt) ? 16u : 0u;
    const size_t astep = (size_t)16 * (2 * I_DIM);
    const __nv_bfloat16* asrc = d_ai + abase + (size_t)lr * (2 * I_DIM) + ls * 8;
    const __nv_bfloat16* wsrc = w2e + (size_t)lr * (2 * I_DIM) + ls * 8;
    const uint32_t sd0 = SWZ(lr * 128 + ls * 16);

    auto load2 = [&](int c) {
        const uint32_t bo = sb + (c & 1) * S2;
        const size_t ko = (size_t)c * 64;
        #pragma unroll
        for (int j = 0; j < 4; j++) {
            CP16(bo + A2O + sd0 + j * 2048, asrc + j * astep + ko, ap[j]);
            CP16(bo + W2O + sd0 + j * 2048, wsrc + j * astep + ko, 16u);
        }
        CP_COMMIT();
    };

    float acc[2][4][4] = {};
    const int ar = lid & 15, ac = (lid >> 4) * 8;
    const int bq = lid >> 3, brr = lid & 7;
    const int bn = (bq >> 1) * 8 + brr, bk = (bq & 1) * 8;

    load2(0);
    const int NCH = I_DIM / 32;   // 16
    for (int c = 0; c < NCH; c++) {
        if (c + 1 < NCH) { load2(c + 1); CP_WAIT(1); }
        else CP_WAIT(0);
        __syncthreads();
        const uint32_t bo = sb + (c & 1) * S2;

        #pragma unroll
        for (int ks = 0; ks < 2; ks++) {
            const int k = ks * 16;
            uint32_t ah[2][4], al[2][4];
            #pragma unroll
            for (int mi = 0; mi < 2; mi++) {
                const int row = wm * 32 + mi * 16 + ar;
                LDM4(ah[mi][0], ah[mi][1], ah[mi][2], ah[mi][3],
                     bo + A2O + SWZ(row * 128 + (k + ac) * 2));
                LDM4(al[mi][0], al[mi][1], al[mi][2], al[mi][3],
                     bo + A2O + SWZ(row * 128 + 64 + (k + ac) * 2));
            }
            #pragma unroll
            for (int nh = 0; nh < 2; nh++) {
                const int row = wn * 32 + nh * 16 + bn;
                uint32_t bh[4], bl[4];
                LDM4(bh[0], bh[1], bh[2], bh[3], bo + W2O + SWZ(row * 128 + (k + bk) * 2));
                LDM4(bl[0], bl[1], bl[2], bl[3], bo + W2O + SWZ(row * 128 + 64 + (k + bk) * 2));
                #pragma unroll
                for (int mi = 0; mi < 2; mi++)
                    #pragma unroll
                    for (int j = 0; j < 2; j++) {
                        const int nj = 2 * nh + j;
                        MMA(acc[mi][nj], ah[mi], bh + 2 * j);
                        MMA(acc[mi][nj], ah[mi], bl + 2 * j);
                        MMA(acc[mi][nj], al[mi], bh + 2 * j);
                    }
            }
        }
        __syncthreads();
    }

    const int g = lid >> 2, tg = lid & 3;
    #pragma unroll
    for (int mi = 0; mi < 2; mi++)
        #pragma unroll
        for (int sub = 0; sub < 2; sub++) {
            const int mrow = wm * 32 + mi * 16 + sub * 8 + g;
            if (m0 + mrow >= cnt) continue;
            const int t = toks[mrow], sk = slots[mrow];
            const float wv = wts[mrow];
            const size_t pbase = ((size_t)t * TOPK + sk) * H_DIM + n0 + wn * 32;
            #pragma unroll
            for (int nj = 0; nj < 4; nj++) {
                float2 o;
                o.x = wv * acc[mi][nj][2 * sub];
                o.y = wv * acc[mi][nj][2 * sub + 1];
                *(float2*)(d_part + pbase + nj * 8 + 2 * tg) = o;
            }
        }
}

// ---------------- combine ----------------
__global__ __launch_bounds__(256) void combine_k(float* __restrict__ out) {
    const int idx = blockIdx.x * blockDim.x + threadIdx.x;
    const int t = idx >> 8, c4 = idx & 255;
    const float4* p = (const float4*)d_part + (size_t)t * TOPK * 256 + c4;
    float4 a = p[0], b = p[256], c = p[512], d = p[768];
    float4 o;
    o.x = a.x + b.x + c.x + d.x;
    o.y = a.y + b.y + c.y + d.y;
    o.z = a.z + b.z + c.z + d.z;
    o.w = a.w + b.w + c.w + d.w;
    ((float4*)out)[idx] = o;
}

// ---------------- launch ----------------
extern "C" void kernel_launch(void* const* d_in, const int* in_sizes, int n_in,
                              void* d_out, int out_size) {
    const float* x  = (const float*)d_in[0];
    const float* gw = (const float*)d_in[1];
    const float* w1 = (const float*)d_in[2];
    const float* w3 = (const float*)d_in[3];
    const float* w2 = (const float*)d_in[4];
    float* out = (float*)d_out;

    cudaFuncSetAttribute(gemm1_t, cudaFuncAttributeMaxDynamicSharedMemorySize, SMEM1);
    cudaFuncSetAttribute(gemm2_t, cudaFuncAttributeMaxDynamicSharedMemorySize, SMEM2);

    init_k<<<1, 32>>>();
    prep_k<<<PREP_W_BLOCKS + PREP_X_BLOCKS + T_TOK, 256>>>(x, gw, w1, w3);
    gemm1_t<<<dim3(CAP / 64, I_DIM / 64, N_EXP + 1), 128, SMEM1>>>(w2);
    gemm2_t<<<dim3(CAP / 64, H_DIM / 64, N_EXP), 128, SMEM2>>>();
    combine_k<<<T_TOK, 256>>>(out);
}

// round 17
// speedup vs baseline: 2.1645x; 1.3394x over previous
#include <cuda_runtime.h>
#include <cuda_fp16.h>
#include <math.h>
#include <stdint.h>

#define T_TOK 2048
#define H_DIM 1024
#define I_DIM 512
#define N_EXP 16
#define TOPK  4
#define CAP   2048

// full-precision sides use interleaved hi/lo fp16: logical row of R elems ->
// 2R fp16; element g: hi at row*2R + (g>>5)*64 + (g&31), lo at +32.
__device__ int   d_cnt[N_EXP];
__device__ int   d_tok[N_EXP * CAP];
__device__ int   d_slot[N_EXP * CAP];
__device__ float d_wt [N_EXP * CAP];
__device__ __half d_xh [(size_t)T_TOK * H_DIM];                 // hi only
__device__ __half d_w1i[(size_t)N_EXP * I_DIM * 2 * H_DIM];     // hi+lo
__device__ __half d_w3i[(size_t)N_EXP * I_DIM * 2 * H_DIM];     // hi+lo
__device__ __half d_w2h[(size_t)N_EXP * H_DIM * I_DIM];         // hi only
__device__ __half d_ai [(size_t)N_EXP * CAP * 2 * I_DIM];       // hi+lo
__device__ float d_part[(size_t)T_TOK * TOPK * H_DIM];

// ---------------- helpers ----------------
#define SWZ(o) ((o) ^ (((o) >> 3) & 0x70))

__device__ __forceinline__ uint32_t smem_u32(const void* p) {
    uint32_t a;
    asm("{ .reg .u64 t; cvta.to.shared.u64 t, %1; cvt.u32.u64 %0, t; }" : "=r"(a) : "l"(p));
    return a;
}

#define CP16(sa, ga, sz) \
    asm volatile("cp.async.cg.shared.global [%0], [%1], 16, %2;" \
                 :: "r"(sa), "l"(ga), "r"(sz) : "memory")
#define CP_COMMIT() asm volatile("cp.async.commit_group;" ::: "memory")
#define CP_WAIT(n)  asm volatile("cp.async.wait_group %0;" :: "n"(n) : "memory")

#define LDM4(r0, r1, r2, r3, a) \
    asm volatile("ldmatrix.sync.aligned.m8n8.x4.shared.b16 {%0,%1,%2,%3}, [%4];" \
                 : "=r"(r0), "=r"(r1), "=r"(r2), "=r"(r3) : "r"(a))

#define MMA(d, a, b) \
    asm volatile("mma.sync.aligned.m16n8k16.row.col.f32.f16.f16.f32 " \
                 "{%0,%1,%2,%3}, {%4,%5,%6,%7}, {%8,%9}, {%0,%1,%2,%3};" \
                 : "+f"((d)[0]), "+f"((d)[1]), "+f"((d)[2]), "+f"((d)[3]) \
                 : "r"((a)[0]), "r"((a)[1]), "r"((a)[2]), "r"((a)[3]), \
                   "r"((b)[0]), "r"((b)[1]))

// gemm1 stage (CTA M64 x N32, KC=64): X 8K | W1 2x4K | W3 2x4K = 24K
#define X1O  0
#define W1O  8192
#define W3O  16384
#define S1   24576
#define SMEM1 (2 * S1)
// gemm2 stage (CTA M64 x N64, KC=64): A 2x8K | W 8K = 24K
#define A2O  0
#define W2O  16384
#define S2   24576
#define SMEM2 (2 * S2)

// ---------------- init ----------------
__global__ void init_k() { if (threadIdx.x < N_EXP) d_cnt[threadIdx.x] = 0; }

// ---------------- fp32 -> fp16 conversions ----------------
template <int RL>
__device__ __forceinline__ void split_store_f16(__half* dst, size_t g4, float4 v) {
    const size_t row = g4 / RL;
    const int g = (int)(g4 % RL);
    const size_t base = row * (size_t)(2 * RL) + ((g >> 5) << 6) + (g & 31);
    __half h0 = __float2half(v.x), h1 = __float2half(v.y);
    __half h2 = __float2half(v.z), h3 = __float2half(v.w);
    __half l0 = __float2half(v.x - __half2float(h0));
    __half l1 = __float2half(v.y - __half2float(h1));
    __half l2 = __float2half(v.z - __half2float(h2));
    __half l3 = __float2half(v.w - __half2float(h3));
    *(__half2*)(dst + base + 0)  = __halves2half2(h0, h1);
    *(__half2*)(dst + base + 2)  = __halves2half2(h2, h3);
    *(__half2*)(dst + base + 32) = __halves2half2(l0, l1);
    *(__half2*)(dst + base + 34) = __halves2half2(l2, l3);
}
__device__ __forceinline__ void plain_store_f16(__half* dst, size_t i4, float4 v) {
    *(__half2*)(dst + i4 * 4 + 0) = __halves2half2(__float2half(v.x), __float2half(v.y));
    *(__half2*)(dst + i4 * 4 + 2) = __halves2half2(__float2half(v.z), __float2half(v.w));
}

// ---------------- fused prep: conv w1/w3 (split) + conv x (plain) + router ----------------
#define PREP_W_BLOCKS 2048
#define PREP_X_BLOCKS 256
__global__ __launch_bounds__(256) void prep_k(const float* __restrict__ x,
                                              const float* __restrict__ gw,
                                              const float* __restrict__ w1,
                                              const float* __restrict__ w3) {
    const int b = blockIdx.x;
    const int tid = threadIdx.x;

    if (b < PREP_W_BLOCKS) {
        const int n = N_EXP * I_DIM * H_DIM / 4;
        for (int i = b * 256 + tid; i < n; i += PREP_W_BLOCKS * 256) {
            split_store_f16<H_DIM>(d_w1i, (size_t)i * 4, ((const float4*)w1)[i]);
            split_store_f16<H_DIM>(d_w3i, (size_t)i * 4, ((const float4*)w3)[i]);
        }
        return;
    }
    if (b < PREP_W_BLOCKS + PREP_X_BLOCKS) {
        const int b2 = b - PREP_W_BLOCKS;
        const int n = T_TOK * H_DIM / 4;
        for (int i = b2 * 256 + tid; i < n; i += PREP_X_BLOCKS * 256)
            plain_store_f16(d_xh, i, ((const float4*)x)[i]);
        return;
    }

    // router: one token per block
    __shared__ float xs[H_DIM];
    __shared__ float lg[N_EXP];
    const int t = b - (PREP_W_BLOCKS + PREP_X_BLOCKS);
    const float* xr = x + (size_t)t * H_DIM;
    for (int i = tid; i < H_DIM / 4; i += 256)
        ((float4*)xs)[i] = ((const float4*)xr)[i];
    __syncthreads();

    const int w = tid >> 5, lane = tid & 31;
    #pragma unroll
    for (int j = 0; j < 2; j++) {
        const int e = w * 2 + j;
        const float* g = gw + (size_t)e * H_DIM;
        float s = 0.f;
        for (int h = lane; h < H_DIM; h += 32) s += xs[h] * g[h];
        #pragma unroll
        for (int o = 16; o; o >>= 1) s += __shfl_xor_sync(0xffffffffu, s, o);
        if (lane == 0) lg[e] = s;
    }
    __syncthreads();

    if (tid == 0) {
        int sel[TOPK]; float sl[TOPK];
        unsigned used = 0;
        for (int k = 0; k < TOPK; k++) {
            float best = -1e30f; int bi = 0;
            for (int e = 0; e < N_EXP; e++)
                if (!((used >> e) & 1u) && lg[e] > best) { best = lg[e]; bi = e; }
            used |= 1u << bi; sel[k] = bi; sl[k] = best;
        }
        float m = sl[0], ex[TOPK], sum = 0.f;
        for (int k = 0; k < TOPK; k++) { ex[k] = expf(sl[k] - m); sum += ex[k]; }
        float inv = 1.f / sum;
        for (int k = 0; k < TOPK; k++) {
            int e = sel[k];
            int pos = atomicAdd(&d_cnt[e], 1);
            d_tok [e * CAP + pos] = t;
            d_slot[e * CAP + pos] = k;
            d_wt  [e * CAP + pos] = ex[k] * inv;
        }
    }
}

// ---------------- gemm1: act = silu(X W1^T) * (X W3^T) ----------------
// CTA M64 x N32, 128 thr, 4 warps (2x2), warp tile M32 x N16.
// 2-term scheme: xh*(wh + wl). KC=64, 2-stage.
// blockIdx.z == N_EXP: co-scheduled plain w2 conversion.
__global__ __launch_bounds__(128, 4) void gemm1_t(const float* __restrict__ w2) {
    const int tid = threadIdx.x;
    if (blockIdx.z == N_EXP) {
        const int bid = blockIdx.x * (I_DIM / 32) + blockIdx.y;   // 0..511
        const int nb = (CAP / 64) * (I_DIM / 32);                 // 512
        const int n = N_EXP * H_DIM * I_DIM / 4;
        for (int i = bid * 128 + tid; i < n; i += nb * 128)
            plain_store_f16(d_w2h, i, ((const float4*)w2)[i]);
        return;
    }

    extern __shared__ char smem[];
    const int e = blockIdx.z, m0 = blockIdx.x * 64, n0 = blockIdx.y * 32;
    const int cnt = d_cnt[e];
    if (m0 >= cnt) return;

    const uint32_t sb = smem_u32(smem);
    const int wid = tid >> 5, lid = tid & 31;
    const int wm = wid & 1, wn = wid >> 1;

    __shared__ int toks[64];
    if (tid < 64) toks[tid] = (m0 + tid < cnt) ? d_tok[e * CAP + m0 + tid] : -1;
    __syncthreads();

    const __half* w1e = d_w1i + ((size_t)e * I_DIM + n0) * (2 * H_DIM);
    const __half* w3e = d_w3i + ((size_t)e * I_DIM + n0) * (2 * H_DIM);

    // loaders: lr in [0,16), ls in [0,8)
    const int lr = tid >> 3, ls = tid & 7;
    unsigned xp[4]; const __half* xs4[4];
    #pragma unroll
    for (int j = 0; j < 4; j++) {
        const int t = toks[lr + 16 * j];
        xp[j] = (t >= 0) ? 16u : 0u;
        xs4[j] = d_xh + (size_t)(t < 0 ? 0 : t) * H_DIM + ls * 8;
    }
    const uint32_t sdX = SWZ(lr * 128 + ls * 16);

    auto load1 = [&](int c) {
        const uint32_t bo = sb + (c & 1) * S1;
        // X: rows lr+16j, 64 fp16 per row
        #pragma unroll
        for (int j = 0; j < 4; j++)
            CP16(bo + X1O + sdX + j * 2048, xs4[j] + (size_t)c * 64, xp[j]);
        // W1/W3: (blk, row) with blk=j>>1, row=lr+16*(j&1), rows<32
        #pragma unroll
        for (int j = 0; j < 4; j++) {
            const int blk = j >> 1, row = lr + 16 * (j & 1);
            const uint32_t sd = SWZ(row * 128 + ls * 16) + blk * 4096;
            const size_t go = (size_t)row * (2 * H_DIM) + (size_t)(2 * c + blk) * 64 + ls * 8;
            CP16(bo + W1O + sd, w1e + go, 16u);
            CP16(bo + W3O + sd, w3e + go, 16u);
        }
        CP_COMMIT();
    };

    float acc1[2][2][4] = {}, acc3[2][2][4] = {};
    const int ar = lid & 15, ac = (lid >> 4) * 8;
    const int bq = lid >> 3, brr = lid & 7;
    const int bn = (bq >> 1) * 8 + brr, bk = (bq & 1) * 8;

    load1(0);
    const int NCH = H_DIM / 64;   // 16
    for (int c = 0; c < NCH; c++) {
        if (c + 1 < NCH) { load1(c + 1); CP_WAIT(1); }
        else CP_WAIT(0);
        __syncthreads();
        const uint32_t bo = sb + (c & 1) * S1;

        #pragma unroll
        for (int ks = 0; ks < 4; ks++) {
            // X hi fragments: full 128B rows, k = ks*16
            uint32_t a[2][4];
            #pragma unroll
            for (int mi = 0; mi < 2; mi++) {
                const int row = wm * 32 + mi * 16 + ar;
                LDM4(a[mi][0], a[mi][1], a[mi][2], a[mi][3],
                     bo + X1O + SWZ(row * 128 + (ks * 16 + ac) * 2));
            }
            // W fragments: sub-tile blk = ks>>1, kk = (ks&1)*16
            const int blk = ks >> 1, kk = (ks & 1) * 16;
            const int row = wn * 16 + bn;
            const uint32_t wb = blk * 4096 + SWZ(row * 128 + (kk + bk) * 2);
            const uint32_t wbl = blk * 4096 + SWZ(row * 128 + 64 + (kk + bk) * 2);
            uint32_t b1h[4], b1l[4], b3h[4], b3l[4];
            LDM4(b1h[0], b1h[1], b1h[2], b1h[3], bo + W1O + wb);
            LDM4(b1l[0], b1l[1], b1l[2], b1l[3], bo + W1O + wbl);
            LDM4(b3h[0], b3h[1], b3h[2], b3h[3], bo + W3O + wb);
            LDM4(b3l[0], b3l[1], b3l[2], b3l[3], bo + W3O + wbl);
            #pragma unroll
            for (int mi = 0; mi < 2; mi++)
                #pragma unroll
                for (int j = 0; j < 2; j++) {
                    MMA(acc1[mi][j], a[mi], b1h + 2 * j);
                    MMA(acc1[mi][j], a[mi], b1l + 2 * j);
                    MMA(acc3[mi][j], a[mi], b3h + 2 * j);
                    MMA(acc3[mi][j], a[mi], b3l + 2 * j);
                }
        }
        __syncthreads();
    }

    // epilogue: silu(acc1)*acc3, store act fp16 hi/lo interleaved
    const int g = lid >> 2, tg = lid & 3;
    #pragma unroll
    for (int mi = 0; mi < 2; mi++)
        #pragma unroll
        for (int sub = 0; sub < 2; sub++) {
            const int mr = wm * 32 + mi * 16 + sub * 8 + g;
            const int m = m0 + mr;
            if (m >= cnt) continue;
            const size_t arow = ((size_t)e * CAP + m) * (2 * I_DIM);
            #pragma unroll
            for (int nj = 0; nj < 2; nj++) {
                const int cc = wn * 16 + nj * 8 + 2 * tg;
                float h0 = acc1[mi][nj][2 * sub], h1 = acc1[mi][nj][2 * sub + 1];
                float g0 = acc3[mi][nj][2 * sub], g1 = acc3[mi][nj][2 * sub + 1];
                float v0 = (h0 / (1.f + expf(-h0))) * g0;
                float v1 = (h1 / (1.f + expf(-h1))) * g1;
                __half a0 = __float2half(v0), a1 = __float2half(v1);
                __half b0 = __float2half(v0 - __half2float(a0));
                __half b1 = __float2half(v1 - __half2float(a1));
                const int gg = n0 + cc;
                const size_t base = arow + ((gg >> 5) << 6) + (gg & 31);
                *(__half2*)(d_ai + base)      = __halves2half2(a0, a1);
                *(__half2*)(d_ai + base + 32) = __halves2half2(b0, b1);
            }
        }
}

// ---------------- gemm2: part[t][slot] = w * (act W2^T), CTA M64 x N64 ----------------
// 2-term scheme: (ah + al)*w2h. KC=64, 2-stage, 128 thr (2x2 warps, warp M32xN32).
__global__ __launch_bounds__(128, 4) void gemm2_t() {
    extern __shared__ char smem[];
    const int e = blockIdx.z, m0 = blockIdx.x * 64, n0 = blockIdx.y * 64;  // n over H
    const int cnt = d_cnt[e];
    if (m0 >= cnt) return;

    const uint32_t sb = smem_u32(smem);
    const int tid = threadIdx.x, wid = tid >> 5, lid = tid & 31;
    const int wm = wid & 1, wn = wid >> 1;

    __shared__ int   toks[64];
    __shared__ int   slots[64];
    __shared__ float wts[64];
    if (tid < 64) {
        const int m = m0 + tid;
        const bool v = (m < cnt);
        toks [tid] = v ? d_tok [e * CAP + m] : 0;
        slots[tid] = v ? d_slot[e * CAP + m] : 0;
        wts  [tid] = v ? d_wt  [e * CAP + m] : 0.f;
    }
    __syncthreads();

    const __half* w2e = d_w2h + ((size_t)e * H_DIM + n0) * I_DIM;
    const size_t abase = ((size_t)e * CAP + m0) * (2 * I_DIM);

    const int lr = tid >> 3, ls = tid & 7;
    unsigned ap[4];
    #pragma unroll
    for (int j = 0; j < 4; j++) ap[j] = (m0 + lr + 16 * j < cnt) ? 16u : 0u;
    const __half* asrc = d_ai + abase + (size_t)lr * (2 * I_DIM) + ls * 8;
    const __half* wsrc = w2e + (size_t)lr * I_DIM + ls * 8;
    const uint32_t sd0 = SWZ(lr * 128 + ls * 16);

    auto load2 = [&](int c) {
        const uint32_t bo = sb + (c & 1) * S2;
        // A: (blk, row): blk=j>>2, row=lr+16*(j&3)
        #pragma unroll
        for (int j = 0; j < 8; j++) {
            const int blk = j >> 2, jr = j & 3;
            const size_t go = (size_t)(16 * jr) * (2 * I_DIM) + (size_t)(2 * c + blk) * 64;
            CP16(bo + A2O + blk * 8192 + sd0 + jr * 2048, asrc + go, ap[jr]);
        }
        // W2: rows lr+16j, plain 64 fp16 per chunk row
        #pragma unroll
        for (int j = 0; j < 4; j++)
            CP16(bo + W2O + sd0 + j * 2048, wsrc + (size_t)(16 * j) * I_DIM + (size_t)c * 64, 16u);
        CP_COMMIT();
    };

    float acc[2][4][4] = {};
    const int ar = lid & 15, ac = (lid >> 4) * 8;
    const int bq = lid >> 3, brr = lid & 7;
    const int bn = (bq >> 1) * 8 + brr, bk = (bq & 1) * 8;

    load2(0);
    const int NCH = I_DIM / 64;   // 8
    for (int c = 0; c < NCH; c++) {
        if (c + 1 < NCH) { load2(c + 1); CP_WAIT(1); }
        else CP_WAIT(0);
        __syncthreads();
        const uint32_t bo = sb + (c & 1) * S2;

        #pragma unroll
        for (int ks = 0; ks < 4; ks++) {
            const int blk = ks >> 1, kk = (ks & 1) * 16;
            uint32_t ah[2][4], al[2][4];
            #pragma unroll
            for (int mi = 0; mi < 2; mi++) {
                const int row = wm * 32 + mi * 16 + ar;
                const uint32_t ab = blk * 8192 + SWZ(row * 128 + (kk + ac) * 2);
                const uint32_t abl = blk * 8192 + SWZ(row * 128 + 64 + (kk + ac) * 2);
                LDM4(ah[mi][0], ah[mi][1], ah[mi][2], ah[mi][3], bo + A2O + ab);
                LDM4(al[mi][0], al[mi][1], al[mi][2], al[mi][3], bo + A2O + abl);
            }
            #pragma unroll
            for (int nh = 0; nh < 2; nh++) {
                const int row = wn * 32 + nh * 16 + bn;
                uint32_t bh[4];
                LDM4(bh[0], bh[1], bh[2], bh[3],
                     bo + W2O + SWZ(row * 128 + (ks * 16 + bk) * 2));
                #pragma unroll
                for (int mi = 0; mi < 2; mi++)
                    #pragma unroll
                    for (int j = 0; j < 2; j++) {
                        const int nj = 2 * nh + j;
                        MMA(acc[mi][nj], ah[mi], bh + 2 * j);
                        MMA(acc[mi][nj], al[mi], bh + 2 * j);
                    }
            }
        }
        __syncthreads();
    }

    const int g = lid >> 2, tg = lid & 3;
    #pragma unroll
    for (int mi = 0; mi < 2; mi++)
        #pragma unroll
        for (int sub = 0; sub < 2; sub++) {
            const int mrow = wm * 32 + mi * 16 + sub * 8 + g;
            if (m0 + mrow >= cnt) continue;
            const int t = toks[mrow], sk = slots[mrow];
            const float wv = wts[mrow];
            const size_t pbase = ((size_t)t * TOPK + sk) * H_DIM + n0 + wn * 32;
            #pragma unroll
            for (int nj = 0; nj < 4; nj++) {
                float2 o;
                o.x = wv * acc[mi][nj][2 * sub];
                o.y = wv * acc[mi][nj][2 * sub + 1];
                *(float2*)(d_part + pbase + nj * 8 + 2 * tg) = o;
            }
        }
}

// ---------------- combine ----------------
__global__ __launch_bounds__(256) void combine_k(float* __restrict__ out) {
    const int idx = blockIdx.x * blockDim.x + threadIdx.x;
    const int t = idx >> 8, c4 = idx & 255;
    const float4* p = (const float4*)d_part + (size_t)t * TOPK * 256 + c4;
    float4 a = p[0], b = p[256], c = p[512], d = p[768];
    float4 o;
    o.x = a.x + b.x + c.x + d.x;
    o.y = a.y + b.y + c.y + d.y;
    o.z = a.z + b.z + c.z + d.z;
    o.w = a.w + b.w + c.w + d.w;
    ((float4*)out)[idx] = o;
}

// ---------------- launch ----------------
extern "C" void kernel_launch(void* const* d_in, const int* in_sizes, int n_in,
                              void* d_out, int out_size) {
    const float* x  = (const float*)d_in[0];
    const float* gw = (const float*)d_in[1];
    const float* w1 = (const float*)d_in[2];
    const float* w3 = (const float*)d_in[3];
    const float* w2 = (const float*)d_in[4];
    float* out = (float*)d_out;

    cudaFuncSetAttribute(gemm1_t, cudaFuncAttributeMaxDynamicSharedMemorySize, SMEM1);
    cudaFuncSetAttribute(gemm2_t, cudaFuncAttributeMaxDynamicSharedMemorySize, SMEM2);

    init_k<<<1, 32>>>();
    prep_k<<<PREP_W_BLOCKS + PREP_X_BLOCKS + T_TOK, 256>>>(x, gw, w1, w3);
    gemm1_t<<<dim3(CAP / 64, I_DIM / 32, N_EXP + 1), 128, SMEM1>>>(w2);
    gemm2_t<<<dim3(CAP / 64, H_DIM / 64, N_EXP), 128, SMEM2>>>();
    combine_k<<<T_TOK, 256>>>(out);
}